// round 12
// baseline (speedup 1.0000x reference)
#include <cuda_runtime.h>
#include <cuda_bf16.h>
#include <cstdint>

#define B_  4
#define C_  256
#define N_  4096
#define NH_ 4
#define HD_ 64

#define QS  (0.125f * 1.44269504f)   // hd^-0.5 * log2(e), folded into Wq/bq

// ---------------- scratch (device globals; no allocations allowed) ----------------
__device__ __nv_bfloat16 g_xT [B_*N_*C_];        // gn(x)    transposed [b][n][c]
__device__ __nv_bfloat16 g_cT [B_*N_*C_];        // gn(cond) transposed [b][n][c]
__device__ __nv_bfloat16 g_qT [B_*NH_*N_*HD_];   // [bh][n][d]  (scale pre-folded)
__device__ __nv_bfloat16 g_kT [B_*NH_*N_*HD_];   // [bh][n][d]
__device__ __nv_bfloat16 g_v  [B_*C_*N_];        // [bh*64+d][n]
__device__ __nv_bfloat16 g_aoT[B_*N_*C_];        // attn out transposed [b][n][c]
__device__ __nv_bfloat16 g_wb [4*C_*C_];         // [q,k,v,o] weights bf16 (wq scaled)

// ---------------- helpers ----------------
__device__ __forceinline__ uint32_t lds32(const __nv_bfloat16* p){
    return *reinterpret_cast<const uint32_t*>(p);
}
__device__ __forceinline__ uint32_t f2b2(float lo, float hi){
    __nv_bfloat162 h = __floats2bfloat162_rn(lo, hi);
    return *reinterpret_cast<uint32_t*>(&h);
}
__device__ __forceinline__ float ex2(float x){
    float y; asm("ex2.approx.f32 %0, %1;" : "=f"(y) : "f"(x)); return y;
}
__device__ __forceinline__ void mma16816(float c[4],
        uint32_t a0,uint32_t a1,uint32_t a2,uint32_t a3,
        uint32_t b0,uint32_t b1){
    asm volatile("mma.sync.aligned.m16n8k16.row.col.f32.bf16.bf16.f32 "
        "{%0,%1,%2,%3}, {%4,%5,%6,%7}, {%8,%9}, {%0,%1,%2,%3};"
        : "+f"(c[0]), "+f"(c[1]), "+f"(c[2]), "+f"(c[3])
        : "r"(a0),"r"(a1),"r"(a2),"r"(a3),"r"(b0),"r"(b1));
}
__device__ __forceinline__ void ldsm4(uint32_t& r0, uint32_t& r1, uint32_t& r2, uint32_t& r3,
                                      const void* p){
    uint32_t a = (uint32_t)__cvta_generic_to_shared(p);
    asm volatile("ldmatrix.sync.aligned.m8n8.x4.shared.b16 {%0,%1,%2,%3}, [%4];"
        : "=r"(r0),"=r"(r1),"=r"(r2),"=r"(r3) : "r"(a));
}
__device__ __forceinline__ void cpasync16(void* dst, const void* src){
    uint32_t d = (uint32_t)__cvta_generic_to_shared(dst);
    asm volatile("cp.async.cg.shared.global [%0], [%1], 16;\n" :: "r"(d), "l"(src));
}
__device__ __forceinline__ void cp_commit(){ asm volatile("cp.async.commit_group;\n"); }

// ---------------- weight fp32->bf16 (Wq pre-scaled by QS) ----------------
__global__ void convert_w_kernel(const float* __restrict__ wq, const float* __restrict__ wk,
                                 const float* __restrict__ wv, const float* __restrict__ wo){
    int i = blockIdx.x*256 + threadIdx.x;
    g_wb[0*C_*C_ + i] = __float2bfloat16(wq[i] * QS);
    g_wb[1*C_*C_ + i] = __float2bfloat16(wk[i]);
    g_wb[2*C_*C_ + i] = __float2bfloat16(wv[i]);
    g_wb[3*C_*C_ + i] = __float2bfloat16(wo[i]);
}

// ---------------- GroupNorm -> transposed bf16 [b][n][c] ----------------
__global__ void __launch_bounds__(256) gn_kernel(
        const float* __restrict__ x, const float* __restrict__ cond,
        const float* __restrict__ gqw, const float* __restrict__ gqb,
        const float* __restrict__ gkw, const float* __restrict__ gkb){
    const int z = blockIdx.y;
    const float* src = z ? cond : x;
    const float* gam = z ? gkw  : gqw;
    const float* bet = z ? gkb  : gqb;
    __nv_bfloat16* dstT = z ? g_cT : g_xT;

    const int grp   = blockIdx.x;              // b*32 + g
    const int batch = grp >> 5;
    const int base  = grp * (8*N_);
    const int cbase = (grp & 31) * 8;

    float s = 0.f, s2 = 0.f;
    const float4* src4 = reinterpret_cast<const float4*>(src + base);
    for (int i = threadIdx.x; i < (8*N_)/4; i += 256){
        float4 v = src4[i];
        s  += v.x + v.y + v.z + v.w;
        s2 += v.x*v.x + v.y*v.y + v.z*v.z + v.w*v.w;
    }
    #pragma unroll
    for (int off = 16; off; off >>= 1){
        s  += __shfl_xor_sync(0xffffffffu, s,  off);
        s2 += __shfl_xor_sync(0xffffffffu, s2, off);
    }
    __shared__ float rs[8], rs2[8];
    int lane = threadIdx.x & 31, warp = threadIdx.x >> 5;
    if (lane == 0){ rs[warp] = s; rs2[warp] = s2; }
    __syncthreads();
    float ts = 0.f, ts2 = 0.f;
    #pragma unroll
    for (int w = 0; w < 8; w++){ ts += rs[w]; ts2 += rs2[w]; }
    const float inv_n = 1.0f / (8.0f*N_);
    float mean = ts * inv_n;
    float var  = ts2 * inv_n - mean*mean;
    float rstd = rsqrtf(var + 1e-5f);

    float a[8], b[8];
    #pragma unroll
    for (int c = 0; c < 8; c++){
        float gv = gam[cbase+c];
        a[c] = rstd * gv;
        b[c] = bet[cbase+c] - mean * rstd * gv;
    }

    for (int n = threadIdx.x; n < N_; n += 256){
        float v[8];
        #pragma unroll
        for (int c = 0; c < 8; c++) v[c] = src[base + c*N_ + n] * a[c] + b[c];
        uint4 o;
        o.x = f2b2(v[0], v[1]); o.y = f2b2(v[2], v[3]);
        o.z = f2b2(v[4], v[5]); o.w = f2b2(v[6], v[7]);
        *reinterpret_cast<uint4*>(&dstT[((size_t)batch*N_ + n)*C_ + cbase]) = o;
    }
}

// ---------------- merged QKV GEMM: out = W @ X (+bias), double-buffered --------
__global__ void __launch_bounds__(256) qkv_kernel(
        const float* __restrict__ bq, const float* __restrict__ bk,
        const float* __restrict__ bv){
    const int z = blockIdx.z;
    const int job = z >> 2, batch = z & 3;
    const __nv_bfloat16* W  = g_wb + job*C_*C_;
    const __nv_bfloat16* XT = (job==0 ? g_xT : g_cT) + (size_t)batch*N_*C_;
    const float* bias = job==0 ? bq : (job==1 ? bk : bv);
    const float bscale = (job==0) ? QS : 1.0f;

    __shared__ __nv_bfloat16 as[2][128][40];   // [m][k]
    __shared__ __nv_bfloat16 bs[2][128][40];   // [n][k]

    const int n0 = blockIdx.x * 128;
    const int m0 = blockIdx.y * 128;

    const int tid  = threadIdx.x;
    const int lane = tid & 31;
    const int warp = tid >> 5;
    const int g = lane >> 2, t = lane & 3;
    const int wm = warp >> 2, wn = warp & 3;

    const int frow = tid >> 2;          // 0..63 (+p*64)
    const int fc8  = (tid & 3) * 8;

    float c[4][4][4];
    #pragma unroll
    for (int mb=0; mb<4; mb++) for (int nb=0; nb<4; nb++)
        #pragma unroll
        for (int r=0; r<4; r++) c[mb][nb][r] = 0.f;

    // prologue: k0 = 0 tile into buffer 0
    #pragma unroll
    for (int p = 0; p < 2; p++){
        int row = frow + p*64;
        cpasync16(&as[0][row][fc8], &W[(m0+row)*C_ + fc8]);
        cpasync16(&bs[0][row][fc8], &XT[(size_t)(n0+row)*C_ + fc8]);
    }
    cp_commit();

    int buf = 0;
    for (int k0 = 0; k0 < C_; k0 += 32){
        if (k0 + 32 < C_){
            #pragma unroll
            for (int p = 0; p < 2; p++){
                int row = frow + p*64;
                cpasync16(&as[buf^1][row][fc8], &W[(m0+row)*C_ + k0 + 32 + fc8]);
                cpasync16(&bs[buf^1][row][fc8], &XT[(size_t)(n0+row)*C_ + k0 + 32 + fc8]);
            }
            cp_commit();
            asm volatile("cp.async.wait_group 1;\n");
        } else {
            asm volatile("cp.async.wait_group 0;\n");
        }
        __syncthreads();

        #pragma unroll
        for (int kk = 0; kk < 32; kk += 16){
            uint32_t A[4][4];
            #pragma unroll
            for (int mb=0; mb<4; mb++){
                int mbase = wm*64 + mb*16;
                A[mb][0] = lds32(&as[buf][mbase+g  ][kk +   t*2]);
                A[mb][1] = lds32(&as[buf][mbase+g+8][kk +   t*2]);
                A[mb][2] = lds32(&as[buf][mbase+g  ][kk+8 + t*2]);
                A[mb][3] = lds32(&as[buf][mbase+g+8][kk+8 + t*2]);
            }
            #pragma unroll
            for (int nb=0; nb<4; nb++){
                uint32_t b0 = lds32(&bs[buf][wn*32+nb*8+g][kk +   t*2]);
                uint32_t b1 = lds32(&bs[buf][wn*32+nb*8+g][kk+8 + t*2]);
                #pragma unroll
                for (int mb=0; mb<4; mb++)
                    mma16816(c[mb][nb], A[mb][0],A[mb][1],A[mb][2],A[mb][3], b0,b1);
            }
        }
        __syncthreads();
        buf ^= 1;
    }

    if (job == 2){
        #pragma unroll
        for (int mb=0; mb<4; mb++){
            int m = m0 + wm*64 + mb*16 + g;
            float bv0 = bias[m], bv8 = bias[m+8];
            #pragma unroll
            for (int nb=0; nb<4; nb++){
                int n = n0 + wn*32 + nb*8 + t*2;
                size_t i0 = ((size_t)batch*C_ + m)*N_ + n;
                size_t i8 = ((size_t)batch*C_ + m + 8)*N_ + n;
                *reinterpret_cast<uint32_t*>(&g_v[i0]) = f2b2(c[mb][nb][0]+bv0, c[mb][nb][1]+bv0);
                *reinterpret_cast<uint32_t*>(&g_v[i8]) = f2b2(c[mb][nb][2]+bv8, c[mb][nb][3]+bv8);
            }
        }
    } else {
        __nv_bfloat16* T = job==0 ? g_qT : g_kT;
        #pragma unroll
        for (int mb=0; mb<4; mb++){
            int m = m0 + wm*64 + mb*16 + g;
            int head = m >> 6, dloc = m & 63;
            size_t rb = (size_t)(batch*NH_ + head) * N_;
            float bv0 = bias[m]*bscale, bv8 = bias[m+8]*bscale;
            #pragma unroll
            for (int nb=0; nb<4; nb++){
                int n = n0 + wn*32 + nb*8 + t*2;
                T[(rb + n  )*HD_ + dloc  ] = __float2bfloat16(c[mb][nb][0] + bv0);
                T[(rb + n+1)*HD_ + dloc  ] = __float2bfloat16(c[mb][nb][1] + bv0);
                T[(rb + n  )*HD_ + dloc+8] = __float2bfloat16(c[mb][nb][2] + bv8);
                T[(rb + n+1)*HD_ + dloc+8] = __float2bfloat16(c[mb][nb][3] + bv8);
            }
        }
    }
}

// ---------------- flash attention: 128 q/block, 8 warps, M=16/warp -------------
// R11 algorithm (static softmax, ldsm fragments, 3-slot single-barrier
// rotation) with the warp layout changed to 8 warps x 16 query rows. Halves
// per-warp registers (s/o: 32 each, qa: 16) -> ~110 regs -> 2 CTAs/SM at 256
// threads = 4 warps/SMSP, so each warp's MUFU/barrier gaps are covered by 3
// co-resident warps instead of 1.
#define TILE_E (64*72)
__global__ void __launch_bounds__(256, 2) attn_kernel(){
    extern __shared__ __nv_bfloat16 dsm[];   // [K0 K1 K2 V0 V1 V2], 64x72 each

    const int bh = blockIdx.y;
    const int n0 = blockIdx.x * 128;
    const int tid  = threadIdx.x;
    const int lane = tid & 31;
    const int warp = tid >> 5;               // 0..7, owns rows [warp*16, +16)
    const int g = lane >> 2, t = lane & 3;

    const int sel   = lane >> 3;
    const int n_off = ((sel >> 1) << 3) + (lane & 7);   // 0..15
    const int c_off = (sel & 1) << 3;                   // 0 or 8

    const __nv_bfloat16* qtb = g_qT + (size_t)bh*N_*HD_;
    const __nv_bfloat16* ktb = g_kT + (size_t)bh*N_*HD_;
    const __nv_bfloat16* vb  = g_v  + (size_t)bh*HD_*N_;

    __nv_bfloat16* KS = dsm;
    __nv_bfloat16* VS = dsm + 3*TILE_E;

    // Q fragments in registers (scale already folded), M=16
    uint32_t qa[4][4];
    {
        const __nv_bfloat16* ra = qtb + (size_t)(n0 + warp*16 + g)*HD_;
        const __nv_bfloat16* rb = ra + 8*HD_;
        #pragma unroll
        for (int kk=0; kk<4; kk++){
            qa[kk][0] = lds32(ra + kk*16     + t*2);
            qa[kk][1] = lds32(rb + kk*16     + t*2);
            qa[kk][2] = lds32(ra + kk*16 + 8 + t*2);
            qa[kk][3] = lds32(rb + kk*16 + 8 + t*2);
        }
    }

    float o[8][4];
    #pragma unroll
    for (int nb=0; nb<8; nb++)
        #pragma unroll
        for (int r=0; r<4; r++) o[nb][r] = 0.f;
    float lsum0 = 0.f, lsum1 = 0.f;

    // fill indexing: 256 threads, K tile = 512 x 16B chunks, V same
    const int frow = tid >> 3;               // 0..31 (+p*32)
    const int fc8  = (tid & 7) * 8;

    // prologue: K,V tile 0 -> slot 0
    #pragma unroll
    for (int p=0; p<2; p++){
        int row = frow + p*32;
        cpasync16(KS + row*72 + fc8, ktb + (size_t)row*HD_ + fc8);
        cpasync16(VS + row*72 + fc8, vb + (size_t)row*N_ + fc8);
    }
    cp_commit();

    int s_cur = 0, s_nxt = 1;
    for (int kt = 0; kt < N_/64; kt++){
        if (kt + 1 < N_/64){
            __nv_bfloat16* kd = KS + s_nxt*TILE_E;
            __nv_bfloat16* vd = VS + s_nxt*TILE_E;
            const __nv_bfloat16* ksrc = ktb + (size_t)(kt+1)*64*HD_;
            const __nv_bfloat16* vsrc = vb + (size_t)(kt+1)*64;
            #pragma unroll
            for (int p=0; p<2; p++){
                int row = frow + p*32;
                cpasync16(kd + row*72 + fc8, ksrc + (size_t)row*HD_ + fc8);
                cpasync16(vd + row*72 + fc8, vsrc + (size_t)row*N_ + fc8);
            }
            cp_commit();
            asm volatile("cp.async.wait_group 1;\n");
        } else {
            asm volatile("cp.async.wait_group 0;\n");
        }
        __syncthreads();   // the ONLY barrier per iteration

        const __nv_bfloat16* kb_s = KS + s_cur*TILE_E;
        const __nv_bfloat16* vb_s = VS + s_cur*TILE_E;

        // ---- S = Q K^T (M=16, N=64) ----
        float s[8][4];
        #pragma unroll
        for (int nb=0; nb<8; nb++)
            #pragma unroll
            for (int r=0; r<4; r++) s[nb][r] = 0.f;
        #pragma unroll
        for (int kk=0; kk<4; kk++){
            #pragma unroll
            for (int nbp=0; nbp<4; nbp++){
                uint32_t b0,b1,b2,b3;
                ldsm4(b0,b1,b2,b3, kb_s + (nbp*16 + n_off)*72 + kk*16 + c_off);
                mma16816(s[2*nbp  ], qa[kk][0],qa[kk][1],qa[kk][2],qa[kk][3], b0,b1);
                mma16816(s[2*nbp+1], qa[kk][0],qa[kk][1],qa[kk][2],qa[kk][3], b2,b3);
            }
        }

        // ---- exp2 + per-lane l accumulation ----
        #pragma unroll
        for (int nb=0; nb<8; nb++){
            s[nb][0] = ex2(s[nb][0]);
            s[nb][1] = ex2(s[nb][1]);
            s[nb][2] = ex2(s[nb][2]);
            s[nb][3] = ex2(s[nb][3]);
            lsum0 += s[nb][0] + s[nb][1];
            lsum1 += s[nb][2] + s[nb][3];
        }

        // ---- O += P V^T ----
        #pragma unroll
        for (int kb=0; kb<4; kb++){
            uint32_t pa0 = f2b2(s[2*kb  ][0], s[2*kb  ][1]);
            uint32_t pa1 = f2b2(s[2*kb  ][2], s[2*kb  ][3]);
            uint32_t pa2 = f2b2(s[2*kb+1][0], s[2*kb+1][1]);
            uint32_t pa3 = f2b2(s[2*kb+1][2], s[2*kb+1][3]);
            #pragma unroll
            for (int nbp=0; nbp<4; nbp++){
                uint32_t b0,b1,b2,b3;
                ldsm4(b0,b1,b2,b3, vb_s + (nbp*16 + n_off)*72 + kb*16 + c_off);
                mma16816(o[2*nbp  ], pa0,pa1,pa2,pa3, b0,b1);
                mma16816(o[2*nbp+1], pa0,pa1,pa2,pa3, b2,b3);
            }
        }

        s_cur = s_nxt;
        s_nxt = (s_nxt == 2) ? 0 : s_nxt + 1;
    }

    // ---- epilogue: cross-lane l reduction, normalize, store [b][n][c] ----
    const int batch = bh >> 2, h = bh & 3;
    __nv_bfloat16* aot = g_aoT + (size_t)batch*N_*C_ + h*64;
    {
        float l0 = lsum0, l1 = lsum1;
        l0 += __shfl_xor_sync(0xffffffffu, l0, 1);
        l0 += __shfl_xor_sync(0xffffffffu, l0, 2);
        l1 += __shfl_xor_sync(0xffffffffu, l1, 1);
        l1 += __shfl_xor_sync(0xffffffffu, l1, 2);
        float i0 = 1.f / l0, i1 = 1.f / l1;
        int r = n0 + warp*16 + g;
        #pragma unroll
        for (int nb=0; nb<8; nb++){
            int d = nb*8 + t*2;
            *reinterpret_cast<uint32_t*>(&aot[(size_t)r    *C_ + d]) =
                f2b2(o[nb][0]*i0, o[nb][1]*i0);
            *reinterpret_cast<uint32_t*>(&aot[(size_t)(r+8)*C_ + d]) =
                f2b2(o[nb][2]*i1, o[nb][3]*i1);
        }
    }
}

// ---------------- output projection + residual (fp32 out), double-buffered -----
__global__ void __launch_bounds__(256) oproj_kernel(
        const float* __restrict__ bias,
        const float* __restrict__ resid,
        float* __restrict__ outf){
    const int batch = blockIdx.z;
    const __nv_bfloat16* W  = g_wb + 3*C_*C_;
    const __nv_bfloat16* XT = g_aoT + (size_t)batch*N_*C_;

    __shared__ __nv_bfloat16 as[2][128][40];
    __shared__ __nv_bfloat16 bs[2][128][40];

    const int n0 = blockIdx.x * 128;
    const int m0 = blockIdx.y * 128;

    const int tid  = threadIdx.x;
    const int lane = tid & 31;
    const int warp = tid >> 5;
    const int g = lane >> 2, t = lane & 3;
    const int wm = warp >> 2, wn = warp & 3;

    const int frow = tid >> 2;
    const int fc8  = (tid & 3) * 8;

    float c[4][4][4];
    #pragma unroll
    for (int mb=0; mb<4; mb++) for (int nb=0; nb<4; nb++)
        #pragma unroll
        for (int r=0; r<4; r++) c[mb][nb][r] = 0.f;

    #pragma unroll
    for (int p = 0; p < 2; p++){
        int row = frow + p*64;
        cpasync16(&as[0][row][fc8], &W[(m0+row)*C_ + fc8]);
        cpasync16(&bs[0][row][fc8], &XT[(size_t)(n0+row)*C_ + fc8]);
    }
    cp_commit();

    int buf = 0;
    for (int k0 = 0; k0 < C_; k0 += 32){
        if (k0 + 32 < C_){
            #pragma unroll
            for (int p = 0; p < 2; p++){
                int row = frow + p*64;
                cpasync16(&as[buf^1][row][fc8], &W[(m0+row)*C_ + k0 + 32 + fc8]);
                cpasync16(&bs[buf^1][row][fc8], &XT[(size_t)(n0+row)*C_ + k0 + 32 + fc8]);
            }
            cp_commit();
            asm volatile("cp.async.wait_group 1;\n");
        } else {
            asm volatile("cp.async.wait_group 0;\n");
        }
        __syncthreads();

        #pragma unroll
        for (int kk = 0; kk < 32; kk += 16){
            uint32_t A[4][4];
            #pragma unroll
            for (int mb=0; mb<4; mb++){
                int mbase = wm*64 + mb*16;
                A[mb][0] = lds32(&as[buf][mbase+g  ][kk +   t*2]);
                A[mb][1] = lds32(&as[buf][mbase+g+8][kk +   t*2]);
                A[mb][2] = lds32(&as[buf][mbase+g  ][kk+8 + t*2]);
                A[mb][3] = lds32(&as[buf][mbase+g+8][kk+8 + t*2]);
            }
            #pragma unroll
            for (int nb=0; nb<4; nb++){
                uint32_t b0 = lds32(&bs[buf][wn*32+nb*8+g][kk +   t*2]);
                uint32_t b1 = lds32(&bs[buf][wn*32+nb*8+g][kk+8 + t*2]);
                #pragma unroll
                for (int mb=0; mb<4; mb++)
                    mma16816(c[mb][nb], A[mb][0],A[mb][1],A[mb][2],A[mb][3], b0,b1);
            }
        }
        __syncthreads();
        buf ^= 1;
    }

    #pragma unroll
    for (int mb=0; mb<4; mb++){
        int m = m0 + wm*64 + mb*16 + g;
        float bv0 = bias[m], bv8 = bias[m+8];
        #pragma unroll
        for (int nb=0; nb<4; nb++){
            int n = n0 + wn*32 + nb*8 + t*2;
            size_t i0 = ((size_t)batch*C_ + m)*N_ + n;
            size_t i8 = ((size_t)batch*C_ + m + 8)*N_ + n;
            float2 r0 = *reinterpret_cast<const float2*>(&resid[i0]);
            float2 r8 = *reinterpret_cast<const float2*>(&resid[i8]);
            *reinterpret_cast<float2*>(&outf[i0]) =
                make_float2(c[mb][nb][0]+bv0+r0.x, c[mb][nb][1]+bv0+r0.y);
            *reinterpret_cast<float2*>(&outf[i8]) =
                make_float2(c[mb][nb][2]+bv8+r8.x, c[mb][nb][3]+bv8+r8.y);
        }
    }
}

// ---------------- launch ----------------
extern "C" void kernel_launch(void* const* d_in, const int* in_sizes, int n_in,
                              void* d_out, int out_size){
    const float* x    = (const float*)d_in[0];
    const float* cond = (const float*)d_in[1];
    const float* gqw  = (const float*)d_in[2];
    const float* gqb  = (const float*)d_in[3];
    const float* gkw  = (const float*)d_in[4];
    const float* gkb  = (const float*)d_in[5];
    const float* wq   = (const float*)d_in[6];
    const float* bq   = (const float*)d_in[7];
    const float* wk   = (const float*)d_in[8];
    const float* bk   = (const float*)d_in[9];
    const float* wv   = (const float*)d_in[10];
    const float* bv   = (const float*)d_in[11];
    const float* wo   = (const float*)d_in[12];
    const float* bo   = (const float*)d_in[13];
    float* out = (float*)d_out;

    const int attn_smem = 6 * TILE_E * (int)sizeof(__nv_bfloat16);   // 55296 B
    cudaFuncSetAttribute(attn_kernel, cudaFuncAttributeMaxDynamicSharedMemorySize, attn_smem);

    convert_w_kernel<<<256, 256>>>(wq, wk, wv, wo);
    gn_kernel<<<dim3(128, 2), 256>>>(x, cond, gqw, gqb, gkw, gkb);
    qkv_kernel<<<dim3(32, 2, 12), 256>>>(bq, bk, bv);
    attn_kernel<<<dim3(32, 16), 256, attn_smem>>>();
    oproj_kernel<<<dim3(32, 2, 4), 256>>>(bo, x, out);
}

// round 13
// speedup vs baseline: 1.0833x; 1.0833x over previous
#include <cuda_runtime.h>
#include <cuda_bf16.h>
#include <cstdint>

#define B_  4
#define C_  256
#define N_  4096
#define NH_ 4
#define HD_ 64

#define QS  (0.125f * 1.44269504f)   // hd^-0.5 * log2(e), folded into Wq/bq

// ---------------- scratch (device globals; no allocations allowed) ----------------
__device__ __nv_bfloat16 g_xT [B_*N_*C_];        // gn(x)    transposed [b][n][c]
__device__ __nv_bfloat16 g_cT [B_*N_*C_];        // gn(cond) transposed [b][n][c]
__device__ __nv_bfloat16 g_qT [B_*NH_*N_*HD_];   // [bh][n][d]  (scale pre-folded)
__device__ __nv_bfloat16 g_kT [B_*NH_*N_*HD_];   // [bh][n][d]
__device__ __nv_bfloat16 g_v  [B_*C_*N_];        // [bh*64+d][n]
__device__ __nv_bfloat16 g_aoT[B_*N_*C_];        // attn out transposed [b][n][c]
__device__ __nv_bfloat16 g_wb [4*C_*C_];         // [q,k,v,o] weights bf16 (wq scaled)

// ---------------- helpers ----------------
__device__ __forceinline__ uint32_t lds32(const __nv_bfloat16* p){
    return *reinterpret_cast<const uint32_t*>(p);
}
__device__ __forceinline__ uint32_t f2b2(float lo, float hi){
    __nv_bfloat162 h = __floats2bfloat162_rn(lo, hi);
    return *reinterpret_cast<uint32_t*>(&h);
}
__device__ __forceinline__ float ex2(float x){
    float y; asm("ex2.approx.f32 %0, %1;" : "=f"(y) : "f"(x)); return y;
}
__device__ __forceinline__ void mma16816(float c[4],
        uint32_t a0,uint32_t a1,uint32_t a2,uint32_t a3,
        uint32_t b0,uint32_t b1){
    asm volatile("mma.sync.aligned.m16n8k16.row.col.f32.bf16.bf16.f32 "
        "{%0,%1,%2,%3}, {%4,%5,%6,%7}, {%8,%9}, {%0,%1,%2,%3};"
        : "+f"(c[0]), "+f"(c[1]), "+f"(c[2]), "+f"(c[3])
        : "r"(a0),"r"(a1),"r"(a2),"r"(a3),"r"(b0),"r"(b1));
}
__device__ __forceinline__ void ldsm4(uint32_t& r0, uint32_t& r1, uint32_t& r2, uint32_t& r3,
                                      const void* p){
    uint32_t a = (uint32_t)__cvta_generic_to_shared(p);
    asm volatile("ldmatrix.sync.aligned.m8n8.x4.shared.b16 {%0,%1,%2,%3}, [%4];"
        : "=r"(r0),"=r"(r1),"=r"(r2),"=r"(r3) : "r"(a));
}
__device__ __forceinline__ void cpasync16(void* dst, const void* src){
    uint32_t d = (uint32_t)__cvta_generic_to_shared(dst);
    asm volatile("cp.async.cg.shared.global [%0], [%1], 16;\n" :: "r"(d), "l"(src));
}
__device__ __forceinline__ void cp_commit(){ asm volatile("cp.async.commit_group;\n"); }

// ---------------- weight fp32->bf16 (Wq pre-scaled by QS) ----------------
__global__ void convert_w_kernel(const float* __restrict__ wq, const float* __restrict__ wk,
                                 const float* __restrict__ wv, const float* __restrict__ wo){
    int i = blockIdx.x*256 + threadIdx.x;
    g_wb[0*C_*C_ + i] = __float2bfloat16(wq[i] * QS);
    g_wb[1*C_*C_ + i] = __float2bfloat16(wk[i]);
    g_wb[2*C_*C_ + i] = __float2bfloat16(wv[i]);
    g_wb[3*C_*C_ + i] = __float2bfloat16(wo[i]);
}

// ---------------- GroupNorm -> transposed bf16 [b][n][c] ----------------
__global__ void __launch_bounds__(256) gn_kernel(
        const float* __restrict__ x, const float* __restrict__ cond,
        const float* __restrict__ gqw, const float* __restrict__ gqb,
        const float* __restrict__ gkw, const float* __restrict__ gkb){
    const int z = blockIdx.y;
    const float* src = z ? cond : x;
    const float* gam = z ? gkw  : gqw;
    const float* bet = z ? gkb  : gqb;
    __nv_bfloat16* dstT = z ? g_cT : g_xT;

    const int grp   = blockIdx.x;              // b*32 + g
    const int batch = grp >> 5;
    const int base  = grp * (8*N_);
    const int cbase = (grp & 31) * 8;

    float s = 0.f, s2 = 0.f;
    const float4* src4 = reinterpret_cast<const float4*>(src + base);
    for (int i = threadIdx.x; i < (8*N_)/4; i += 256){
        float4 v = src4[i];
        s  += v.x + v.y + v.z + v.w;
        s2 += v.x*v.x + v.y*v.y + v.z*v.z + v.w*v.w;
    }
    #pragma unroll
    for (int off = 16; off; off >>= 1){
        s  += __shfl_xor_sync(0xffffffffu, s,  off);
        s2 += __shfl_xor_sync(0xffffffffu, s2, off);
    }
    __shared__ float rs[8], rs2[8];
    int lane = threadIdx.x & 31, warp = threadIdx.x >> 5;
    if (lane == 0){ rs[warp] = s; rs2[warp] = s2; }
    __syncthreads();
    float ts = 0.f, ts2 = 0.f;
    #pragma unroll
    for (int w = 0; w < 8; w++){ ts += rs[w]; ts2 += rs2[w]; }
    const float inv_n = 1.0f / (8.0f*N_);
    float mean = ts * inv_n;
    float var  = ts2 * inv_n - mean*mean;
    float rstd = rsqrtf(var + 1e-5f);

    float a[8], b[8];
    #pragma unroll
    for (int c = 0; c < 8; c++){
        float gv = gam[cbase+c];
        a[c] = rstd * gv;
        b[c] = bet[cbase+c] - mean * rstd * gv;
    }

    for (int n = threadIdx.x; n < N_; n += 256){
        float v[8];
        #pragma unroll
        for (int c = 0; c < 8; c++) v[c] = src[base + c*N_ + n] * a[c] + b[c];
        uint4 o;
        o.x = f2b2(v[0], v[1]); o.y = f2b2(v[2], v[3]);
        o.z = f2b2(v[4], v[5]); o.w = f2b2(v[6], v[7]);
        *reinterpret_cast<uint4*>(&dstT[((size_t)batch*N_ + n)*C_ + cbase]) = o;
    }
}

// ---------------- merged QKV GEMM: out = W @ X (+bias), double-buffered --------
__global__ void __launch_bounds__(256) qkv_kernel(
        const float* __restrict__ bq, const float* __restrict__ bk,
        const float* __restrict__ bv){
    const int z = blockIdx.z;
    const int job = z >> 2, batch = z & 3;
    const __nv_bfloat16* W  = g_wb + job*C_*C_;
    const __nv_bfloat16* XT = (job==0 ? g_xT : g_cT) + (size_t)batch*N_*C_;
    const float* bias = job==0 ? bq : (job==1 ? bk : bv);
    const float bscale = (job==0) ? QS : 1.0f;

    __shared__ __nv_bfloat16 as[2][128][40];   // [m][k]
    __shared__ __nv_bfloat16 bs[2][128][40];   // [n][k]

    const int n0 = blockIdx.x * 128;
    const int m0 = blockIdx.y * 128;

    const int tid  = threadIdx.x;
    const int lane = tid & 31;
    const int warp = tid >> 5;
    const int g = lane >> 2, t = lane & 3;
    const int wm = warp >> 2, wn = warp & 3;

    const int frow = tid >> 2;          // 0..63 (+p*64)
    const int fc8  = (tid & 3) * 8;

    float c[4][4][4];
    #pragma unroll
    for (int mb=0; mb<4; mb++) for (int nb=0; nb<4; nb++)
        #pragma unroll
        for (int r=0; r<4; r++) c[mb][nb][r] = 0.f;

    // prologue: k0 = 0 tile into buffer 0
    #pragma unroll
    for (int p = 0; p < 2; p++){
        int row = frow + p*64;
        cpasync16(&as[0][row][fc8], &W[(m0+row)*C_ + fc8]);
        cpasync16(&bs[0][row][fc8], &XT[(size_t)(n0+row)*C_ + fc8]);
    }
    cp_commit();

    int buf = 0;
    for (int k0 = 0; k0 < C_; k0 += 32){
        if (k0 + 32 < C_){
            #pragma unroll
            for (int p = 0; p < 2; p++){
                int row = frow + p*64;
                cpasync16(&as[buf^1][row][fc8], &W[(m0+row)*C_ + k0 + 32 + fc8]);
                cpasync16(&bs[buf^1][row][fc8], &XT[(size_t)(n0+row)*C_ + k0 + 32 + fc8]);
            }
            cp_commit();
            asm volatile("cp.async.wait_group 1;\n");
        } else {
            asm volatile("cp.async.wait_group 0;\n");
        }
        __syncthreads();

        #pragma unroll
        for (int kk = 0; kk < 32; kk += 16){
            uint32_t A[4][4];
            #pragma unroll
            for (int mb=0; mb<4; mb++){
                int mbase = wm*64 + mb*16;
                A[mb][0] = lds32(&as[buf][mbase+g  ][kk +   t*2]);
                A[mb][1] = lds32(&as[buf][mbase+g+8][kk +   t*2]);
                A[mb][2] = lds32(&as[buf][mbase+g  ][kk+8 + t*2]);
                A[mb][3] = lds32(&as[buf][mbase+g+8][kk+8 + t*2]);
            }
            #pragma unroll
            for (int nb=0; nb<4; nb++){
                uint32_t b0 = lds32(&bs[buf][wn*32+nb*8+g][kk +   t*2]);
                uint32_t b1 = lds32(&bs[buf][wn*32+nb*8+g][kk+8 + t*2]);
                #pragma unroll
                for (int mb=0; mb<4; mb++)
                    mma16816(c[mb][nb], A[mb][0],A[mb][1],A[mb][2],A[mb][3], b0,b1);
            }
        }
        __syncthreads();
        buf ^= 1;
    }

    if (job == 2){
        #pragma unroll
        for (int mb=0; mb<4; mb++){
            int m = m0 + wm*64 + mb*16 + g;
            float bv0 = bias[m], bv8 = bias[m+8];
            #pragma unroll
            for (int nb=0; nb<4; nb++){
                int n = n0 + wn*32 + nb*8 + t*2;
                size_t i0 = ((size_t)batch*C_ + m)*N_ + n;
                size_t i8 = ((size_t)batch*C_ + m + 8)*N_ + n;
                *reinterpret_cast<uint32_t*>(&g_v[i0]) = f2b2(c[mb][nb][0]+bv0, c[mb][nb][1]+bv0);
                *reinterpret_cast<uint32_t*>(&g_v[i8]) = f2b2(c[mb][nb][2]+bv8, c[mb][nb][3]+bv8);
            }
        }
    } else {
        __nv_bfloat16* T = job==0 ? g_qT : g_kT;
        #pragma unroll
        for (int mb=0; mb<4; mb++){
            int m = m0 + wm*64 + mb*16 + g;
            int head = m >> 6, dloc = m & 63;
            size_t rb = (size_t)(batch*NH_ + head) * N_;
            float bv0 = bias[m]*bscale, bv8 = bias[m+8]*bscale;
            #pragma unroll
            for (int nb=0; nb<4; nb++){
                int n = n0 + wn*32 + nb*8 + t*2;
                T[(rb + n  )*HD_ + dloc  ] = __float2bfloat16(c[mb][nb][0] + bv0);
                T[(rb + n+1)*HD_ + dloc  ] = __float2bfloat16(c[mb][nb][1] + bv0);
                T[(rb + n  )*HD_ + dloc+8] = __float2bfloat16(c[mb][nb][2] + bv8);
                T[(rb + n+1)*HD_ + dloc+8] = __float2bfloat16(c[mb][nb][3] + bv8);
            }
        }
    }
}

// ---------------- flash attention: 64 q/block, 4 warps, M=16/warp, 4 CTAs/SM ---
// R11 rotation/static softmax with 64-query CTAs: every SMSP hosts 4 warps
// from 4 INDEPENDENT CTAs (no shared barrier between them), so softmax/pack
// and barrier gaps of one warp are covered by mma streams of the other three.
// Per-warp inner code identical to the proven M=16 path; 3-slot single-barrier
// rotation identical to R11. smem 54KB x 4 CTAs = 216KB/SM.
#define TILE_E (64*72)
__global__ void __launch_bounds__(128, 4) attn_kernel(){
    extern __shared__ __nv_bfloat16 dsm[];   // [K0 K1 K2 V0 V1 V2], 64x72 each

    const int bh = blockIdx.y;
    const int n0 = blockIdx.x * 64;
    const int tid  = threadIdx.x;
    const int lane = tid & 31;
    const int warp = tid >> 5;               // 0..3, owns rows [warp*16, +16)
    const int g = lane >> 2, t = lane & 3;

    const int sel   = lane >> 3;
    const int n_off = ((sel >> 1) << 3) + (lane & 7);   // 0..15
    const int c_off = (sel & 1) << 3;                   // 0 or 8

    const __nv_bfloat16* qtb = g_qT + (size_t)bh*N_*HD_;
    const __nv_bfloat16* ktb = g_kT + (size_t)bh*N_*HD_;
    const __nv_bfloat16* vb  = g_v  + (size_t)bh*HD_*N_;

    __nv_bfloat16* KS = dsm;
    __nv_bfloat16* VS = dsm + 3*TILE_E;

    // Q fragments in registers (scale already folded), M=16
    uint32_t qa[4][4];
    {
        const __nv_bfloat16* ra = qtb + (size_t)(n0 + warp*16 + g)*HD_;
        const __nv_bfloat16* rb = ra + 8*HD_;
        #pragma unroll
        for (int kk=0; kk<4; kk++){
            qa[kk][0] = lds32(ra + kk*16     + t*2);
            qa[kk][1] = lds32(rb + kk*16     + t*2);
            qa[kk][2] = lds32(ra + kk*16 + 8 + t*2);
            qa[kk][3] = lds32(rb + kk*16 + 8 + t*2);
        }
    }

    float o[8][4];
    #pragma unroll
    for (int nb=0; nb<8; nb++)
        #pragma unroll
        for (int r=0; r<4; r++) o[nb][r] = 0.f;
    float lsum0 = 0.f, lsum1 = 0.f;

    // fill indexing: 128 threads, K tile = 512 x 16B chunks, V same
    const int frow = tid >> 3;               // 0..15 (+p*16)
    const int fc8  = (tid & 7) * 8;

    // prologue: K,V tile 0 -> slot 0
    #pragma unroll
    for (int p=0; p<4; p++){
        int row = frow + p*16;
        cpasync16(KS + row*72 + fc8, ktb + (size_t)row*HD_ + fc8);
        cpasync16(VS + row*72 + fc8, vb + (size_t)row*N_ + fc8);
    }
    cp_commit();

    int s_cur = 0, s_nxt = 1;
    for (int kt = 0; kt < N_/64; kt++){
        if (kt + 1 < N_/64){
            __nv_bfloat16* kd = KS + s_nxt*TILE_E;
            __nv_bfloat16* vd = VS + s_nxt*TILE_E;
            const __nv_bfloat16* ksrc = ktb + (size_t)(kt+1)*64*HD_;
            const __nv_bfloat16* vsrc = vb + (size_t)(kt+1)*64;
            #pragma unroll
            for (int p=0; p<4; p++){
                int row = frow + p*16;
                cpasync16(kd + row*72 + fc8, ksrc + (size_t)row*HD_ + fc8);
                cpasync16(vd + row*72 + fc8, vsrc + (size_t)row*N_ + fc8);
            }
            cp_commit();
            asm volatile("cp.async.wait_group 1;\n");
        } else {
            asm volatile("cp.async.wait_group 0;\n");
        }
        __syncthreads();   // the ONLY barrier per iteration (intra-CTA only)

        const __nv_bfloat16* kb_s = KS + s_cur*TILE_E;
        const __nv_bfloat16* vb_s = VS + s_cur*TILE_E;

        // ---- S = Q K^T (M=16, N=64) ----
        float s[8][4];
        #pragma unroll
        for (int nb=0; nb<8; nb++)
            #pragma unroll
            for (int r=0; r<4; r++) s[nb][r] = 0.f;
        #pragma unroll
        for (int kk=0; kk<4; kk++){
            #pragma unroll
            for (int nbp=0; nbp<4; nbp++){
                uint32_t b0,b1,b2,b3;
                ldsm4(b0,b1,b2,b3, kb_s + (nbp*16 + n_off)*72 + kk*16 + c_off);
                mma16816(s[2*nbp  ], qa[kk][0],qa[kk][1],qa[kk][2],qa[kk][3], b0,b1);
                mma16816(s[2*nbp+1], qa[kk][0],qa[kk][1],qa[kk][2],qa[kk][3], b2,b3);
            }
        }

        // ---- exp2 + per-lane l accumulation ----
        #pragma unroll
        for (int nb=0; nb<8; nb++){
            s[nb][0] = ex2(s[nb][0]);
            s[nb][1] = ex2(s[nb][1]);
            s[nb][2] = ex2(s[nb][2]);
            s[nb][3] = ex2(s[nb][3]);
            lsum0 += s[nb][0] + s[nb][1];
            lsum1 += s[nb][2] + s[nb][3];
        }

        // ---- O += P V^T ----
        #pragma unroll
        for (int kb=0; kb<4; kb++){
            uint32_t pa0 = f2b2(s[2*kb  ][0], s[2*kb  ][1]);
            uint32_t pa1 = f2b2(s[2*kb  ][2], s[2*kb  ][3]);
            uint32_t pa2 = f2b2(s[2*kb+1][0], s[2*kb+1][1]);
            uint32_t pa3 = f2b2(s[2*kb+1][2], s[2*kb+1][3]);
            #pragma unroll
            for (int nbp=0; nbp<4; nbp++){
                uint32_t b0,b1,b2,b3;
                ldsm4(b0,b1,b2,b3, vb_s + (nbp*16 + n_off)*72 + kb*16 + c_off);
                mma16816(o[2*nbp  ], pa0,pa1,pa2,pa3, b0,b1);
                mma16816(o[2*nbp+1], pa0,pa1,pa2,pa3, b2,b3);
            }
        }

        s_cur = s_nxt;
        s_nxt = (s_nxt == 2) ? 0 : s_nxt + 1;
    }

    // ---- epilogue: cross-lane l reduction, normalize, store [b][n][c] ----
    const int batch = bh >> 2, h = bh & 3;
    __nv_bfloat16* aot = g_aoT + (size_t)batch*N_*C_ + h*64;
    {
        float l0 = lsum0, l1 = lsum1;
        l0 += __shfl_xor_sync(0xffffffffu, l0, 1);
        l0 += __shfl_xor_sync(0xffffffffu, l0, 2);
        l1 += __shfl_xor_sync(0xffffffffu, l1, 1);
        l1 += __shfl_xor_sync(0xffffffffu, l1, 2);
        float i0 = 1.f / l0, i1 = 1.f / l1;
        int r = n0 + warp*16 + g;
        #pragma unroll
        for (int nb=0; nb<8; nb++){
            int d = nb*8 + t*2;
            *reinterpret_cast<uint32_t*>(&aot[(size_t)r    *C_ + d]) =
                f2b2(o[nb][0]*i0, o[nb][1]*i0);
            *reinterpret_cast<uint32_t*>(&aot[(size_t)(r+8)*C_ + d]) =
                f2b2(o[nb][2]*i1, o[nb][3]*i1);
        }
    }
}

// ---------------- output projection + residual (fp32 out), double-buffered -----
__global__ void __launch_bounds__(256) oproj_kernel(
        const float* __restrict__ bias,
        const float* __restrict__ resid,
        float* __restrict__ outf){
    const int batch = blockIdx.z;
    const __nv_bfloat16* W  = g_wb + 3*C_*C_;
    const __nv_bfloat16* XT = g_aoT + (size_t)batch*N_*C_;

    __shared__ __nv_bfloat16 as[2][128][40];
    __shared__ __nv_bfloat16 bs[2][128][40];

    const int n0 = blockIdx.x * 128;
    const int m0 = blockIdx.y * 128;

    const int tid  = threadIdx.x;
    const int lane = tid & 31;
    const int warp = tid >> 5;
    const int g = lane >> 2, t = lane & 3;
    const int wm = warp >> 2, wn = warp & 3;

    const int frow = tid >> 2;
    const int fc8  = (tid & 3) * 8;

    float c[4][4][4];
    #pragma unroll
    for (int mb=0; mb<4; mb++) for (int nb=0; nb<4; nb++)
        #pragma unroll
        for (int r=0; r<4; r++) c[mb][nb][r] = 0.f;

    #pragma unroll
    for (int p = 0; p < 2; p++){
        int row = frow + p*64;
        cpasync16(&as[0][row][fc8], &W[(m0+row)*C_ + fc8]);
        cpasync16(&bs[0][row][fc8], &XT[(size_t)(n0+row)*C_ + fc8]);
    }
    cp_commit();

    int buf = 0;
    for (int k0 = 0; k0 < C_; k0 += 32){
        if (k0 + 32 < C_){
            #pragma unroll
            for (int p = 0; p < 2; p++){
                int row = frow + p*64;
                cpasync16(&as[buf^1][row][fc8], &W[(m0+row)*C_ + k0 + 32 + fc8]);
                cpasync16(&bs[buf^1][row][fc8], &XT[(size_t)(n0+row)*C_ + k0 + 32 + fc8]);
            }
            cp_commit();
            asm volatile("cp.async.wait_group 1;\n");
        } else {
            asm volatile("cp.async.wait_group 0;\n");
        }
        __syncthreads();

        #pragma unroll
        for (int kk = 0; kk < 32; kk += 16){
            uint32_t A[4][4];
            #pragma unroll
            for (int mb=0; mb<4; mb++){
                int mbase = wm*64 + mb*16;
                A[mb][0] = lds32(&as[buf][mbase+g  ][kk +   t*2]);
                A[mb][1] = lds32(&as[buf][mbase+g+8][kk +   t*2]);
                A[mb][2] = lds32(&as[buf][mbase+g  ][kk+8 + t*2]);
                A[mb][3] = lds32(&as[buf][mbase+g+8][kk+8 + t*2]);
            }
            #pragma unroll
            for (int nb=0; nb<4; nb++){
                uint32_t b0 = lds32(&bs[buf][wn*32+nb*8+g][kk +   t*2]);
                uint32_t b1 = lds32(&bs[buf][wn*32+nb*8+g][kk+8 + t*2]);
                #pragma unroll
                for (int mb=0; mb<4; mb++)
                    mma16816(c[mb][nb], A[mb][0],A[mb][1],A[mb][2],A[mb][3], b0,b1);
            }
        }
        __syncthreads();
        buf ^= 1;
    }

    #pragma unroll
    for (int mb=0; mb<4; mb++){
        int m = m0 + wm*64 + mb*16 + g;
        float bv0 = bias[m], bv8 = bias[m+8];
        #pragma unroll
        for (int nb=0; nb<4; nb++){
            int n = n0 + wn*32 + nb*8 + t*2;
            size_t i0 = ((size_t)batch*C_ + m)*N_ + n;
            size_t i8 = ((size_t)batch*C_ + m + 8)*N_ + n;
            float2 r0 = *reinterpret_cast<const float2*>(&resid[i0]);
            float2 r8 = *reinterpret_cast<const float2*>(&resid[i8]);
            *reinterpret_cast<float2*>(&outf[i0]) =
                make_float2(c[mb][nb][0]+bv0+r0.x, c[mb][nb][1]+bv0+r0.y);
            *reinterpret_cast<float2*>(&outf[i8]) =
                make_float2(c[mb][nb][2]+bv8+r8.x, c[mb][nb][3]+bv8+r8.y);
        }
    }
}

// ---------------- launch ----------------
extern "C" void kernel_launch(void* const* d_in, const int* in_sizes, int n_in,
                              void* d_out, int out_size){
    const float* x    = (const float*)d_in[0];
    const float* cond = (const float*)d_in[1];
    const float* gqw  = (const float*)d_in[2];
    const float* gqb  = (const float*)d_in[3];
    const float* gkw  = (const float*)d_in[4];
    const float* gkb  = (const float*)d_in[5];
    const float* wq   = (const float*)d_in[6];
    const float* bq   = (const float*)d_in[7];
    const float* wk   = (const float*)d_in[8];
    const float* bk   = (const float*)d_in[9];
    const float* wv   = (const float*)d_in[10];
    const float* bv   = (const float*)d_in[11];
    const float* wo   = (const float*)d_in[12];
    const float* bo   = (const float*)d_in[13];
    float* out = (float*)d_out;

    const int attn_smem = 6 * TILE_E * (int)sizeof(__nv_bfloat16);   // 55296 B
    cudaFuncSetAttribute(attn_kernel, cudaFuncAttributeMaxDynamicSharedMemorySize, attn_smem);

    convert_w_kernel<<<256, 256>>>(wq, wk, wv, wo);
    gn_kernel<<<dim3(128, 2), 256>>>(x, cond, gqw, gqb, gkw, gkb);
    qkv_kernel<<<dim3(32, 2, 12), 256>>>(bq, bk, bv);
    attn_kernel<<<dim3(64, 16), 128, attn_smem>>>();
    oproj_kernel<<<dim3(32, 2, 4), 256>>>(bo, x, out);
}

// round 15
// speedup vs baseline: 1.1067x; 1.0216x over previous
#include <cuda_runtime.h>
#include <cuda_bf16.h>
#include <cstdint>

#define B_  4
#define C_  256
#define N_  4096
#define NH_ 4
#define HD_ 64

#define QS  (0.125f * 1.44269504f)   // hd^-0.5 * log2(e), folded into Wq/bq

// ---------------- scratch (device globals; no allocations allowed) ----------------
__device__ __nv_bfloat16 g_xT [B_*N_*C_];        // gn(x)    transposed [b][n][c]
__device__ __nv_bfloat16 g_cT [B_*N_*C_];        // gn(cond) transposed [b][n][c]
__device__ __nv_bfloat16 g_qT [B_*NH_*N_*HD_];   // [bh][n][d]  (scale pre-folded)
__device__ __nv_bfloat16 g_kT [B_*NH_*N_*HD_];   // [bh][n][d]
__device__ __nv_bfloat16 g_v  [B_*C_*N_];        // [bh*64+d][n]
__device__ __nv_bfloat16 g_aoT[B_*N_*C_];        // attn out transposed [b][n][c]
__device__ __nv_bfloat16 g_wb [4*C_*C_];         // [q,k,v,o] weights bf16 (wq scaled)

// ---------------- helpers ----------------
__device__ __forceinline__ uint32_t lds32(const __nv_bfloat16* p){
    return *reinterpret_cast<const uint32_t*>(p);
}
__device__ __forceinline__ uint32_t f2b2(float lo, float hi){
    __nv_bfloat162 h = __floats2bfloat162_rn(lo, hi);
    return *reinterpret_cast<uint32_t*>(&h);
}
__device__ __forceinline__ float ex2(float x){
    float y; asm("ex2.approx.f32 %0, %1;" : "=f"(y) : "f"(x)); return y;
}
__device__ __forceinline__ void mma16816(float c[4],
        uint32_t a0,uint32_t a1,uint32_t a2,uint32_t a3,
        uint32_t b0,uint32_t b1){
    asm volatile("mma.sync.aligned.m16n8k16.row.col.f32.bf16.bf16.f32 "
        "{%0,%1,%2,%3}, {%4,%5,%6,%7}, {%8,%9}, {%0,%1,%2,%3};"
        : "+f"(c[0]), "+f"(c[1]), "+f"(c[2]), "+f"(c[3])
        : "r"(a0),"r"(a1),"r"(a2),"r"(a3),"r"(b0),"r"(b1));
}
__device__ __forceinline__ void ldsm4(uint32_t& r0, uint32_t& r1, uint32_t& r2, uint32_t& r3,
                                      const void* p){
    uint32_t a = (uint32_t)__cvta_generic_to_shared(p);
    asm volatile("ldmatrix.sync.aligned.m8n8.x4.shared.b16 {%0,%1,%2,%3}, [%4];"
        : "=r"(r0),"=r"(r1),"=r"(r2),"=r"(r3) : "r"(a));
}
__device__ __forceinline__ void cpasync16(void* dst, const void* src){
    uint32_t d = (uint32_t)__cvta_generic_to_shared(dst);
    asm volatile("cp.async.cg.shared.global [%0], [%1], 16;\n" :: "r"(d), "l"(src));
}
__device__ __forceinline__ void cp_commit(){ asm volatile("cp.async.commit_group;\n"); }

// ---------------- GroupNorm -> transposed bf16 [b][n][c]  (+ fused weight cvt) --
// grid (128, 3): y==0 -> gn(x), y==1 -> gn(cond), y==2 -> weight fp32->bf16
__global__ void __launch_bounds__(256) gn_kernel(
        const float* __restrict__ x, const float* __restrict__ cond,
        const float* __restrict__ gqw, const float* __restrict__ gqb,
        const float* __restrict__ gkw, const float* __restrict__ gkb,
        const float* __restrict__ wq, const float* __restrict__ wk,
        const float* __restrict__ wv, const float* __restrict__ wo){
    const int z = blockIdx.y;

    if (z == 2){   // weight conversion: 128 CTAs x 256 thr, 2 elems each per matrix
        int i = blockIdx.x*256 + threadIdx.x;
        #pragma unroll
        for (int p = 0; p < 2; p++){
            int idx = i + p*32768;
            g_wb[0*C_*C_ + idx] = __float2bfloat16(wq[idx] * QS);
            g_wb[1*C_*C_ + idx] = __float2bfloat16(wk[idx]);
            g_wb[2*C_*C_ + idx] = __float2bfloat16(wv[idx]);
            g_wb[3*C_*C_ + idx] = __float2bfloat16(wo[idx]);
        }
        return;
    }

    const float* src = z ? cond : x;
    const float* gam = z ? gkw  : gqw;
    const float* bet = z ? gkb  : gqb;
    __nv_bfloat16* dstT = z ? g_cT : g_xT;

    const int grp   = blockIdx.x;              // b*32 + g
    const int batch = grp >> 5;
    const int base  = grp * (8*N_);
    const int cbase = (grp & 31) * 8;

    float s = 0.f, s2 = 0.f;
    const float4* src4 = reinterpret_cast<const float4*>(src + base);
    for (int i = threadIdx.x; i < (8*N_)/4; i += 256){
        float4 v = src4[i];
        s  += v.x + v.y + v.z + v.w;
        s2 += v.x*v.x + v.y*v.y + v.z*v.z + v.w*v.w;
    }
    #pragma unroll
    for (int off = 16; off; off >>= 1){
        s  += __shfl_xor_sync(0xffffffffu, s,  off);
        s2 += __shfl_xor_sync(0xffffffffu, s2, off);
    }
    __shared__ float rs[8], rs2[8];
    int lane = threadIdx.x & 31, warp = threadIdx.x >> 5;
    if (lane == 0){ rs[warp] = s; rs2[warp] = s2; }
    __syncthreads();
    float ts = 0.f, ts2 = 0.f;
    #pragma unroll
    for (int w = 0; w < 8; w++){ ts += rs[w]; ts2 += rs2[w]; }
    const float inv_n = 1.0f / (8.0f*N_);
    float mean = ts * inv_n;
    float var  = ts2 * inv_n - mean*mean;
    float rstd = rsqrtf(var + 1e-5f);

    float a[8], b[8];
    #pragma unroll
    for (int c = 0; c < 8; c++){
        float gv = gam[cbase+c];
        a[c] = rstd * gv;
        b[c] = bet[cbase+c] - mean * rstd * gv;
    }

    for (int n = threadIdx.x; n < N_; n += 256){
        float v[8];
        #pragma unroll
        for (int c = 0; c < 8; c++) v[c] = src[base + c*N_ + n] * a[c] + b[c];
        uint4 o;
        o.x = f2b2(v[0], v[1]); o.y = f2b2(v[2], v[3]);
        o.z = f2b2(v[4], v[5]); o.w = f2b2(v[6], v[7]);
        *reinterpret_cast<uint4*>(&dstT[((size_t)batch*N_ + n)*C_ + cbase]) = o;
    }
}

// ---------------- merged QKV GEMM: out = W @ X (+bias), double-buffered --------
__global__ void __launch_bounds__(256) qkv_kernel(
        const float* __restrict__ bq, const float* __restrict__ bk,
        const float* __restrict__ bv){
    const int z = blockIdx.z;
    const int job = z >> 2, batch = z & 3;
    const __nv_bfloat16* W  = g_wb + job*C_*C_;
    const __nv_bfloat16* XT = (job==0 ? g_xT : g_cT) + (size_t)batch*N_*C_;
    const float* bias = job==0 ? bq : (job==1 ? bk : bv);
    const float bscale = (job==0) ? QS : 1.0f;

    __shared__ __nv_bfloat16 as[2][128][40];   // [m][k]
    __shared__ __nv_bfloat16 bs[2][128][40];   // [n][k]

    const int n0 = blockIdx.x * 128;
    const int m0 = blockIdx.y * 128;

    const int tid  = threadIdx.x;
    const int lane = tid & 31;
    const int warp = tid >> 5;
    const int g = lane >> 2, t = lane & 3;
    const int wm = warp >> 2, wn = warp & 3;

    const int frow = tid >> 2;          // 0..63 (+p*64)
    const int fc8  = (tid & 3) * 8;

    float c[4][4][4];
    #pragma unroll
    for (int mb=0; mb<4; mb++) for (int nb=0; nb<4; nb++)
        #pragma unroll
        for (int r=0; r<4; r++) c[mb][nb][r] = 0.f;

    // prologue: k0 = 0 tile into buffer 0
    #pragma unroll
    for (int p = 0; p < 2; p++){
        int row = frow + p*64;
        cpasync16(&as[0][row][fc8], &W[(m0+row)*C_ + fc8]);
        cpasync16(&bs[0][row][fc8], &XT[(size_t)(n0+row)*C_ + fc8]);
    }
    cp_commit();

    int buf = 0;
    for (int k0 = 0; k0 < C_; k0 += 32){
        if (k0 + 32 < C_){
            #pragma unroll
            for (int p = 0; p < 2; p++){
                int row = frow + p*64;
                cpasync16(&as[buf^1][row][fc8], &W[(m0+row)*C_ + k0 + 32 + fc8]);
                cpasync16(&bs[buf^1][row][fc8], &XT[(size_t)(n0+row)*C_ + k0 + 32 + fc8]);
            }
            cp_commit();
            asm volatile("cp.async.wait_group 1;\n");
        } else {
            asm volatile("cp.async.wait_group 0;\n");
        }
        __syncthreads();

        #pragma unroll
        for (int kk = 0; kk < 32; kk += 16){
            uint32_t A[4][4];
            #pragma unroll
            for (int mb=0; mb<4; mb++){
                int mbase = wm*64 + mb*16;
                A[mb][0] = lds32(&as[buf][mbase+g  ][kk +   t*2]);
                A[mb][1] = lds32(&as[buf][mbase+g+8][kk +   t*2]);
                A[mb][2] = lds32(&as[buf][mbase+g  ][kk+8 + t*2]);
                A[mb][3] = lds32(&as[buf][mbase+g+8][kk+8 + t*2]);
            }
            #pragma unroll
            for (int nb=0; nb<4; nb++){
                uint32_t b0 = lds32(&bs[buf][wn*32+nb*8+g][kk +   t*2]);
                uint32_t b1 = lds32(&bs[buf][wn*32+nb*8+g][kk+8 + t*2]);
                #pragma unroll
                for (int mb=0; mb<4; mb++)
                    mma16816(c[mb][nb], A[mb][0],A[mb][1],A[mb][2],A[mb][3], b0,b1);
            }
        }
        __syncthreads();
        buf ^= 1;
    }

    if (job == 2){
        #pragma unroll
        for (int mb=0; mb<4; mb++){
            int m = m0 + wm*64 + mb*16 + g;
            float bv0 = bias[m], bv8 = bias[m+8];
            #pragma unroll
            for (int nb=0; nb<4; nb++){
                int n = n0 + wn*32 + nb*8 + t*2;
                size_t i0 = ((size_t)batch*C_ + m)*N_ + n;
                size_t i8 = ((size_t)batch*C_ + m + 8)*N_ + n;
                *reinterpret_cast<uint32_t*>(&g_v[i0]) = f2b2(c[mb][nb][0]+bv0, c[mb][nb][1]+bv0);
                *reinterpret_cast<uint32_t*>(&g_v[i8]) = f2b2(c[mb][nb][2]+bv8, c[mb][nb][3]+bv8);
            }
        }
    } else {
        __nv_bfloat16* T = job==0 ? g_qT : g_kT;
        #pragma unroll
        for (int mb=0; mb<4; mb++){
            int m = m0 + wm*64 + mb*16 + g;
            int head = m >> 6, dloc = m & 63;
            size_t rb = (size_t)(batch*NH_ + head) * N_;
            float bv0 = bias[m]*bscale, bv8 = bias[m+8]*bscale;
            #pragma unroll
            for (int nb=0; nb<4; nb++){
                int n = n0 + wn*32 + nb*8 + t*2;
                T[(rb + n  )*HD_ + dloc  ] = __float2bfloat16(c[mb][nb][0] + bv0);
                T[(rb + n+1)*HD_ + dloc  ] = __float2bfloat16(c[mb][nb][1] + bv0);
                T[(rb + n  )*HD_ + dloc+8] = __float2bfloat16(c[mb][nb][2] + bv8);
                T[(rb + n+1)*HD_ + dloc+8] = __float2bfloat16(c[mb][nb][3] + bv8);
            }
        }
    }
}

// ---------------- flash attention: 64 q/block, 4 warps, M=16/warp, 4 CTAs/SM ---
// R13 winner verbatim: static softmax, ldsm fragments, 3-slot single-barrier
// rotation; every SMSP hosts 4 warps from 4 independent CTAs.
#define TILE_E (64*72)
__global__ void __launch_bounds__(128, 4) attn_kernel(){
    extern __shared__ __nv_bfloat16 dsm[];   // [K0 K1 K2 V0 V1 V2], 64x72 each

    const int bh = blockIdx.y;
    const int n0 = blockIdx.x * 64;
    const int tid  = threadIdx.x;
    const int lane = tid & 31;
    const int warp = tid >> 5;               // 0..3, owns rows [warp*16, +16)
    const int g = lane >> 2, t = lane & 3;

    const int sel   = lane >> 3;
    const int n_off = ((sel >> 1) << 3) + (lane & 7);   // 0..15
    const int c_off = (sel & 1) << 3;                   // 0 or 8

    const __nv_bfloat16* qtb = g_qT + (size_t)bh*N_*HD_;
    const __nv_bfloat16* ktb = g_kT + (size_t)bh*N_*HD_;
    const __nv_bfloat16* vb  = g_v  + (size_t)bh*HD_*N_;

    __nv_bfloat16* KS = dsm;
    __nv_bfloat16* VS = dsm + 3*TILE_E;

    // Q fragments in registers (scale already folded), M=16
    uint32_t qa[4][4];
    {
        const __nv_bfloat16* ra = qtb + (size_t)(n0 + warp*16 + g)*HD_;
        const __nv_bfloat16* rb = ra + 8*HD_;
        #pragma unroll
        for (int kk=0; kk<4; kk++){
            qa[kk][0] = lds32(ra + kk*16     + t*2);
            qa[kk][1] = lds32(rb + kk*16     + t*2);
            qa[kk][2] = lds32(ra + kk*16 + 8 + t*2);
            qa[kk][3] = lds32(rb + kk*16 + 8 + t*2);
        }
    }

    float o[8][4];
    #pragma unroll
    for (int nb=0; nb<8; nb++)
        #pragma unroll
        for (int r=0; r<4; r++) o[nb][r] = 0.f;
    float lsum0 = 0.f, lsum1 = 0.f;

    // fill indexing: 128 threads, K tile = 512 x 16B chunks, V same
    const int frow = tid >> 3;               // 0..15 (+p*16)
    const int fc8  = (tid & 7) * 8;

    // prologue: K,V tile 0 -> slot 0
    #pragma unroll
    for (int p=0; p<4; p++){
        int row = frow + p*16;
        cpasync16(KS + row*72 + fc8, ktb + (size_t)row*HD_ + fc8);
        cpasync16(VS + row*72 + fc8, vb + (size_t)row*N_ + fc8);
    }
    cp_commit();

    int s_cur = 0, s_nxt = 1;
    for (int kt = 0; kt < N_/64; kt++){
        if (kt + 1 < N_/64){
            __nv_bfloat16* kd = KS + s_nxt*TILE_E;
            __nv_bfloat16* vd = VS + s_nxt*TILE_E;
            const __nv_bfloat16* ksrc = ktb + (size_t)(kt+1)*64*HD_;
            const __nv_bfloat16* vsrc = vb + (size_t)(kt+1)*64;
            #pragma unroll
            for (int p=0; p<4; p++){
                int row = frow + p*16;
                cpasync16(kd + row*72 + fc8, ksrc + (size_t)row*HD_ + fc8);
                cpasync16(vd + row*72 + fc8, vsrc + (size_t)row*N_ + fc8);
            }
            cp_commit();
            asm volatile("cp.async.wait_group 1;\n");
        } else {
            asm volatile("cp.async.wait_group 0;\n");
        }
        __syncthreads();   // the ONLY barrier per iteration (intra-CTA only)

        const __nv_bfloat16* kb_s = KS + s_cur*TILE_E;
        const __nv_bfloat16* vb_s = VS + s_cur*TILE_E;

        // ---- S = Q K^T (M=16, N=64) ----
        float s[8][4];
        #pragma unroll
        for (int nb=0; nb<8; nb++)
            #pragma unroll
            for (int r=0; r<4; r++) s[nb][r] = 0.f;
        #pragma unroll
        for (int kk=0; kk<4; kk++){
            #pragma unroll
            for (int nbp=0; nbp<4; nbp++){
                uint32_t b0,b1,b2,b3;
                ldsm4(b0,b1,b2,b3, kb_s + (nbp*16 + n_off)*72 + kk*16 + c_off);
                mma16816(s[2*nbp  ], qa[kk][0],qa[kk][1],qa[kk][2],qa[kk][3], b0,b1);
                mma16816(s[2*nbp+1], qa[kk][0],qa[kk][1],qa[kk][2],qa[kk][3], b2,b3);
            }
        }

        // ---- exp2 + per-lane l accumulation ----
        #pragma unroll
        for (int nb=0; nb<8; nb++){
            s[nb][0] = ex2(s[nb][0]);
            s[nb][1] = ex2(s[nb][1]);
            s[nb][2] = ex2(s[nb][2]);
            s[nb][3] = ex2(s[nb][3]);
            lsum0 += s[nb][0] + s[nb][1];
            lsum1 += s[nb][2] + s[nb][3];
        }

        // ---- O += P V^T ----
        #pragma unroll
        for (int kb=0; kb<4; kb++){
            uint32_t pa0 = f2b2(s[2*kb  ][0], s[2*kb  ][1]);
            uint32_t pa1 = f2b2(s[2*kb  ][2], s[2*kb  ][3]);
            uint32_t pa2 = f2b2(s[2*kb+1][0], s[2*kb+1][1]);
            uint32_t pa3 = f2b2(s[2*kb+1][2], s[2*kb+1][3]);
            #pragma unroll
            for (int nbp=0; nbp<4; nbp++){
                uint32_t b0,b1,b2,b3;
                ldsm4(b0,b1,b2,b3, vb_s + (nbp*16 + n_off)*72 + kb*16 + c_off);
                mma16816(o[2*nbp  ], pa0,pa1,pa2,pa3, b0,b1);
                mma16816(o[2*nbp+1], pa0,pa1,pa2,pa3, b2,b3);
            }
        }

        s_cur = s_nxt;
        s_nxt = (s_nxt == 2) ? 0 : s_nxt + 1;
    }

    // ---- epilogue: cross-lane l reduction, normalize, store [b][n][c] ----
    const int batch = bh >> 2, h = bh & 3;
    __nv_bfloat16* aot = g_aoT + (size_t)batch*N_*C_ + h*64;
    {
        float l0 = lsum0, l1 = lsum1;
        l0 += __shfl_xor_sync(0xffffffffu, l0, 1);
        l0 += __shfl_xor_sync(0xffffffffu, l0, 2);
        l1 += __shfl_xor_sync(0xffffffffu, l1, 1);
        l1 += __shfl_xor_sync(0xffffffffu, l1, 2);
        float i0 = 1.f / l0, i1 = 1.f / l1;
        int r = n0 + warp*16 + g;
        #pragma unroll
        for (int nb=0; nb<8; nb++){
            int d = nb*8 + t*2;
            *reinterpret_cast<uint32_t*>(&aot[(size_t)r    *C_ + d]) =
                f2b2(o[nb][0]*i0, o[nb][1]*i0);
            *reinterpret_cast<uint32_t*>(&aot[(size_t)(r+8)*C_ + d]) =
                f2b2(o[nb][2]*i1, o[nb][3]*i1);
        }
    }
}

// ---------------- output projection + residual (fp32 out), double-buffered -----
__global__ void __launch_bounds__(256) oproj_kernel(
        const float* __restrict__ bias,
        const float* __restrict__ resid,
        float* __restrict__ outf){
    const int batch = blockIdx.z;
    const __nv_bfloat16* W  = g_wb + 3*C_*C_;
    const __nv_bfloat16* XT = g_aoT + (size_t)batch*N_*C_;

    __shared__ __nv_bfloat16 as[2][128][40];
    __shared__ __nv_bfloat16 bs[2][128][40];

    const int n0 = blockIdx.x * 128;
    const int m0 = blockIdx.y * 128;

    const int tid  = threadIdx.x;
    const int lane = tid & 31;
    const int warp = tid >> 5;
    const int g = lane >> 2, t = lane & 3;
    const int wm = warp >> 2, wn = warp & 3;

    const int frow = tid >> 2;
    const int fc8  = (tid & 3) * 8;

    float c[4][4][4];
    #pragma unroll
    for (int mb=0; mb<4; mb++) for (int nb=0; nb<4; nb++)
        #pragma unroll
        for (int r=0; r<4; r++) c[mb][nb][r] = 0.f;

    #pragma unroll
    for (int p = 0; p < 2; p++){
        int row = frow + p*64;
        cpasync16(&as[0][row][fc8], &W[(m0+row)*C_ + fc8]);
        cpasync16(&bs[0][row][fc8], &XT[(size_t)(n0+row)*C_ + fc8]);
    }
    cp_commit();

    int buf = 0;
    for (int k0 = 0; k0 < C_; k0 += 32){
        if (k0 + 32 < C_){
            #pragma unroll
            for (int p = 0; p < 2; p++){
                int row = frow + p*64;
                cpasync16(&as[buf^1][row][fc8], &W[(m0+row)*C_ + k0 + 32 + fc8]);
                cpasync16(&bs[buf^1][row][fc8], &XT[(size_t)(n0+row)*C_ + k0 + 32 + fc8]);
            }
            cp_commit();
            asm volatile("cp.async.wait_group 1;\n");
        } else {
            asm volatile("cp.async.wait_group 0;\n");
        }
        __syncthreads();

        #pragma unroll
        for (int kk = 0; kk < 32; kk += 16){
            uint32_t A[4][4];
            #pragma unroll
            for (int mb=0; mb<4; mb++){
                int mbase = wm*64 + mb*16;
                A[mb][0] = lds32(&as[buf][mbase+g  ][kk +   t*2]);
                A[mb][1] = lds32(&as[buf][mbase+g+8][kk +   t*2]);
                A[mb][2] = lds32(&as[buf][mbase+g  ][kk+8 + t*2]);
                A[mb][3] = lds32(&as[buf][mbase+g+8][kk+8 + t*2]);
            }
            #pragma unroll
            for (int nb=0; nb<4; nb++){
                uint32_t b0 = lds32(&bs[buf][wn*32+nb*8+g][kk +   t*2]);
                uint32_t b1 = lds32(&bs[buf][wn*32+nb*8+g][kk+8 + t*2]);
                #pragma unroll
                for (int mb=0; mb<4; mb++)
                    mma16816(c[mb][nb], A[mb][0],A[mb][1],A[mb][2],A[mb][3], b0,b1);
            }
        }
        __syncthreads();
        buf ^= 1;
    }

    #pragma unroll
    for (int mb=0; mb<4; mb++){
        int m = m0 + wm*64 + mb*16 + g;
        float bv0 = bias[m], bv8 = bias[m+8];
        #pragma unroll
        for (int nb=0; nb<4; nb++){
            int n = n0 + wn*32 + nb*8 + t*2;
            size_t i0 = ((size_t)batch*C_ + m)*N_ + n;
            size_t i8 = ((size_t)batch*C_ + m + 8)*N_ + n;
            float2 r0 = *reinterpret_cast<const float2*>(&resid[i0]);
            float2 r8 = *reinterpret_cast<const float2*>(&resid[i8]);
            *reinterpret_cast<float2*>(&outf[i0]) =
                make_float2(c[mb][nb][0]+bv0+r0.x, c[mb][nb][1]+bv0+r0.y);
            *reinterpret_cast<float2*>(&outf[i8]) =
                make_float2(c[mb][nb][2]+bv8+r8.x, c[mb][nb][3]+bv8+r8.y);
        }
    }
}

// ---------------- launch ----------------
extern "C" void kernel_launch(void* const* d_in, const int* in_sizes, int n_in,
                              void* d_out, int out_size){
    const float* x    = (const float*)d_in[0];
    const float* cond = (const float*)d_in[1];
    const float* gqw  = (const float*)d_in[2];
    const float* gqb  = (const float*)d_in[3];
    const float* gkw  = (const float*)d_in[4];
    const float* gkb  = (const float*)d_in[5];
    const float* wq   = (const float*)d_in[6];
    const float* bq   = (const float*)d_in[7];
    const float* wk   = (const float*)d_in[8];
    const float* bk   = (const float*)d_in[9];
    const float* wv   = (const float*)d_in[10];
    const float* bv   = (const float*)d_in[11];
    const float* wo   = (const float*)d_in[12];
    const float* bo   = (const float*)d_in[13];
    float* out = (float*)d_out;

    const int attn_smem = 6 * TILE_E * (int)sizeof(__nv_bfloat16);   // 55296 B
    cudaFuncSetAttribute(attn_kernel, cudaFuncAttributeMaxDynamicSharedMemorySize, attn_smem);

    gn_kernel<<<dim3(128, 3), 256>>>(x, cond, gqw, gqb, gkw, gkb, wq, wk, wv, wo);
    qkv_kernel<<<dim3(32, 2, 12), 256>>>(bq, bk, bv);
    attn_kernel<<<dim3(64, 16), 128, attn_smem>>>();
    oproj_kernel<<<dim3(32, 2, 4), 256>>>(bo, x, out);
}

// round 16
// speedup vs baseline: 1.1214x; 1.0133x over previous
#include <cuda_runtime.h>
#include <cuda_bf16.h>
#include <cstdint>

#define B_  4
#define C_  256
#define N_  4096
#define NH_ 4
#define HD_ 64

#define QS  (0.125f * 1.44269504f)   // hd^-0.5 * log2(e), folded into Wq/bq

// ---------------- scratch (device globals; no allocations allowed) ----------------
__device__ __nv_bfloat16 g_xT [B_*N_*C_];        // gn(x)    transposed [b][n][c]
__device__ __nv_bfloat16 g_cT [B_*N_*C_];        // gn(cond) transposed [b][n][c]
__device__ __nv_bfloat16 g_qT [B_*NH_*N_*HD_];   // [bh][n][d]  (scale pre-folded)
__device__ __nv_bfloat16 g_kT [B_*NH_*N_*HD_];   // [bh][n][d]
__device__ __nv_bfloat16 g_v  [B_*C_*N_];        // [bh*64+d][n]
__device__ __nv_bfloat16 g_aoT[B_*N_*C_];        // attn out transposed [b][n][c]
__device__ __nv_bfloat16 g_wb [4*C_*C_];         // [q,k,v,o] weights bf16 (wq scaled)

// ---------------- helpers ----------------
__device__ __forceinline__ uint32_t lds32(const __nv_bfloat16* p){
    return *reinterpret_cast<const uint32_t*>(p);
}
__device__ __forceinline__ uint32_t f2b2(float lo, float hi){
    __nv_bfloat162 h = __floats2bfloat162_rn(lo, hi);
    return *reinterpret_cast<uint32_t*>(&h);
}
__device__ __forceinline__ float ex2(float x){
    float y; asm("ex2.approx.f32 %0, %1;" : "=f"(y) : "f"(x)); return y;
}
__device__ __forceinline__ void mma16816(float c[4],
        uint32_t a0,uint32_t a1,uint32_t a2,uint32_t a3,
        uint32_t b0,uint32_t b1){
    asm volatile("mma.sync.aligned.m16n8k16.row.col.f32.bf16.bf16.f32 "
        "{%0,%1,%2,%3}, {%4,%5,%6,%7}, {%8,%9}, {%0,%1,%2,%3};"
        : "+f"(c[0]), "+f"(c[1]), "+f"(c[2]), "+f"(c[3])
        : "r"(a0),"r"(a1),"r"(a2),"r"(a3),"r"(b0),"r"(b1));
}
__device__ __forceinline__ void ldsm4(uint32_t& r0, uint32_t& r1, uint32_t& r2, uint32_t& r3,
                                      const void* p){
    uint32_t a = (uint32_t)__cvta_generic_to_shared(p);
    asm volatile("ldmatrix.sync.aligned.m8n8.x4.shared.b16 {%0,%1,%2,%3}, [%4];"
        : "=r"(r0),"=r"(r1),"=r"(r2),"=r"(r3) : "r"(a));
}
__device__ __forceinline__ void cpasync16(void* dst, const void* src){
    uint32_t d = (uint32_t)__cvta_generic_to_shared(dst);
    asm volatile("cp.async.cg.shared.global [%0], [%1], 16;\n" :: "r"(d), "l"(src));
}
__device__ __forceinline__ void cp_commit(){ asm volatile("cp.async.commit_group;\n"); }

// ---------------- GroupNorm -> transposed bf16 [b][n][c]  (+ fused weight cvt) --
// grid (128, 3): y==0 -> gn(x), y==1 -> gn(cond), y==2 -> weight fp32->bf16
__global__ void __launch_bounds__(256) gn_kernel(
        const float* __restrict__ x, const float* __restrict__ cond,
        const float* __restrict__ gqw, const float* __restrict__ gqb,
        const float* __restrict__ gkw, const float* __restrict__ gkb,
        const float* __restrict__ wq, const float* __restrict__ wk,
        const float* __restrict__ wv, const float* __restrict__ wo){
    const int z = blockIdx.y;

    if (z == 2){   // weight conversion: 128 CTAs x 256 thr, 2 elems each per matrix
        int i = blockIdx.x*256 + threadIdx.x;
        #pragma unroll
        for (int p = 0; p < 2; p++){
            int idx = i + p*32768;
            g_wb[0*C_*C_ + idx] = __float2bfloat16(wq[idx] * QS);
            g_wb[1*C_*C_ + idx] = __float2bfloat16(wk[idx]);
            g_wb[2*C_*C_ + idx] = __float2bfloat16(wv[idx]);
            g_wb[3*C_*C_ + idx] = __float2bfloat16(wo[idx]);
        }
        return;
    }

    const float* src = z ? cond : x;
    const float* gam = z ? gkw  : gqw;
    const float* bet = z ? gkb  : gqb;
    __nv_bfloat16* dstT = z ? g_cT : g_xT;

    const int grp   = blockIdx.x;              // b*32 + g
    const int batch = grp >> 5;
    const int base  = grp * (8*N_);
    const int cbase = (grp & 31) * 8;

    float s = 0.f, s2 = 0.f;
    const float4* src4 = reinterpret_cast<const float4*>(src + base);
    for (int i = threadIdx.x; i < (8*N_)/4; i += 256){
        float4 v = src4[i];
        s  += v.x + v.y + v.z + v.w;
        s2 += v.x*v.x + v.y*v.y + v.z*v.z + v.w*v.w;
    }
    #pragma unroll
    for (int off = 16; off; off >>= 1){
        s  += __shfl_xor_sync(0xffffffffu, s,  off);
        s2 += __shfl_xor_sync(0xffffffffu, s2, off);
    }
    __shared__ float rs[8], rs2[8];
    int lane = threadIdx.x & 31, warp = threadIdx.x >> 5;
    if (lane == 0){ rs[warp] = s; rs2[warp] = s2; }
    __syncthreads();
    float ts = 0.f, ts2 = 0.f;
    #pragma unroll
    for (int w = 0; w < 8; w++){ ts += rs[w]; ts2 += rs2[w]; }
    const float inv_n = 1.0f / (8.0f*N_);
    float mean = ts * inv_n;
    float var  = ts2 * inv_n - mean*mean;
    float rstd = rsqrtf(var + 1e-5f);

    float a[8], b[8];
    #pragma unroll
    for (int c = 0; c < 8; c++){
        float gv = gam[cbase+c];
        a[c] = rstd * gv;
        b[c] = bet[cbase+c] - mean * rstd * gv;
    }

    for (int n = threadIdx.x; n < N_; n += 256){
        float v[8];
        #pragma unroll
        for (int c = 0; c < 8; c++) v[c] = src[base + c*N_ + n] * a[c] + b[c];
        uint4 o;
        o.x = f2b2(v[0], v[1]); o.y = f2b2(v[2], v[3]);
        o.z = f2b2(v[4], v[5]); o.w = f2b2(v[6], v[7]);
        *reinterpret_cast<uint4*>(&dstT[((size_t)batch*N_ + n)*C_ + cbase]) = o;
    }
}

// ---------------- GEMM tile constants (qkv / oproj shared) ----------------
#define GS_ROW   40                  // padded k-pitch (bf16)
#define GS_SLOT  (128*GS_ROW)        // one 128x32(+pad) matrix tile
#define GS_TOT   (8*GS_SLOT)         // 4 slots A + 4 slots B
// fill one slot pair: 256 threads, 2x (row, 8 bf16) chunks per matrix
#define GEMM_FILL(AS_, BS_, Wp, Xp, koff)                                   \
    do {                                                                    \
        _Pragma("unroll")                                                   \
        for (int p = 0; p < 2; p++){                                        \
            int row = frow + p*64;                                          \
            cpasync16((AS_) + row*GS_ROW + fc8, (Wp) + (size_t)row*C_ + (koff) + fc8); \
            cpasync16((BS_) + row*GS_ROW + fc8, (Xp) + (size_t)row*C_ + (koff) + fc8); \
        }                                                                   \
    } while(0)

// ---------------- merged QKV GEMM: depth-2 pipeline, 4 slots, 1 barrier --------
__global__ void __launch_bounds__(256) qkv_kernel(
        const float* __restrict__ bq, const float* __restrict__ bk,
        const float* __restrict__ bv){
    extern __shared__ __nv_bfloat16 gsm[];
    const int z = blockIdx.z;
    const int job = z >> 2, batch = z & 3;
    const __nv_bfloat16* W  = g_wb + job*C_*C_;
    const __nv_bfloat16* XT = (job==0 ? g_xT : g_cT) + (size_t)batch*N_*C_;
    const float* bias = job==0 ? bq : (job==1 ? bk : bv);
    const float bscale = (job==0) ? QS : 1.0f;

    __nv_bfloat16* AS = gsm;
    __nv_bfloat16* BS = gsm + 4*GS_SLOT;

    const int n0 = blockIdx.x * 128;
    const int m0 = blockIdx.y * 128;

    const int tid  = threadIdx.x;
    const int lane = tid & 31;
    const int warp = tid >> 5;
    const int g = lane >> 2, t = lane & 3;
    const int wm = warp >> 2, wn = warp & 3;

    const int frow = tid >> 2;          // 0..63 (+p*64)
    const int fc8  = (tid & 3) * 8;

    const __nv_bfloat16* Wp = W + (size_t)m0*C_;
    const __nv_bfloat16* Xp = XT + (size_t)n0*C_;

    float c[4][4][4];
    #pragma unroll
    for (int mb=0; mb<4; mb++) for (int nb=0; nb<4; nb++)
        #pragma unroll
        for (int r=0; r<4; r++) c[mb][nb][r] = 0.f;

    // prologue: tiles 0 and 1
    GEMM_FILL(AS, BS, Wp, Xp, 0);
    cp_commit();
    GEMM_FILL(AS + GS_SLOT, BS + GS_SLOT, Wp, Xp, 32);
    cp_commit();

    for (int kt = 0; kt < 8; kt++){
        if (kt + 2 < 8){
            int sl = (kt + 2) & 3;
            GEMM_FILL(AS + sl*GS_SLOT, BS + sl*GS_SLOT, Wp, Xp, (kt+2)*32);
        }
        cp_commit();                               // empty groups keep counts aligned
        asm volatile("cp.async.wait_group 2;\n");  // tile kt complete
        __syncthreads();                           // the ONLY barrier per iteration

        const __nv_bfloat16* as = AS + (kt & 3)*GS_SLOT;
        const __nv_bfloat16* bs = BS + (kt & 3)*GS_SLOT;

        #pragma unroll
        for (int kk = 0; kk < 32; kk += 16){
            uint32_t A[4][4];
            #pragma unroll
            for (int mb=0; mb<4; mb++){
                int mbase = wm*64 + mb*16;
                A[mb][0] = lds32(as + (mbase+g  )*GS_ROW + kk +   t*2);
                A[mb][1] = lds32(as + (mbase+g+8)*GS_ROW + kk +   t*2);
                A[mb][2] = lds32(as + (mbase+g  )*GS_ROW + kk+8 + t*2);
                A[mb][3] = lds32(as + (mbase+g+8)*GS_ROW + kk+8 + t*2);
            }
            #pragma unroll
            for (int nb=0; nb<4; nb++){
                uint32_t b0 = lds32(bs + (wn*32+nb*8+g)*GS_ROW + kk +   t*2);
                uint32_t b1 = lds32(bs + (wn*32+nb*8+g)*GS_ROW + kk+8 + t*2);
                #pragma unroll
                for (int mb=0; mb<4; mb++)
                    mma16816(c[mb][nb], A[mb][0],A[mb][1],A[mb][2],A[mb][3], b0,b1);
            }
        }
    }

    if (job == 2){
        #pragma unroll
        for (int mb=0; mb<4; mb++){
            int m = m0 + wm*64 + mb*16 + g;
            float bv0 = bias[m], bv8 = bias[m+8];
            #pragma unroll
            for (int nb=0; nb<4; nb++){
                int n = n0 + wn*32 + nb*8 + t*2;
                size_t i0 = ((size_t)batch*C_ + m)*N_ + n;
                size_t i8 = ((size_t)batch*C_ + m + 8)*N_ + n;
                *reinterpret_cast<uint32_t*>(&g_v[i0]) = f2b2(c[mb][nb][0]+bv0, c[mb][nb][1]+bv0);
                *reinterpret_cast<uint32_t*>(&g_v[i8]) = f2b2(c[mb][nb][2]+bv8, c[mb][nb][3]+bv8);
            }
        }
    } else {
        __nv_bfloat16* T = job==0 ? g_qT : g_kT;
        #pragma unroll
        for (int mb=0; mb<4; mb++){
            int m = m0 + wm*64 + mb*16 + g;
            int head = m >> 6, dloc = m & 63;
            size_t rb = (size_t)(batch*NH_ + head) * N_;
            float bv0 = bias[m]*bscale, bv8 = bias[m+8]*bscale;
            #pragma unroll
            for (int nb=0; nb<4; nb++){
                int n = n0 + wn*32 + nb*8 + t*2;
                T[(rb + n  )*HD_ + dloc  ] = __float2bfloat16(c[mb][nb][0] + bv0);
                T[(rb + n+1)*HD_ + dloc  ] = __float2bfloat16(c[mb][nb][1] + bv0);
                T[(rb + n  )*HD_ + dloc+8] = __float2bfloat16(c[mb][nb][2] + bv8);
                T[(rb + n+1)*HD_ + dloc+8] = __float2bfloat16(c[mb][nb][3] + bv8);
            }
        }
    }
}

// ---------------- flash attention: 64 q/block, 4 warps, M=16/warp, 4 CTAs/SM ---
// R13/R15 winner verbatim: static softmax, ldsm fragments, 3-slot single-barrier
// rotation; every SMSP hosts 4 warps from 4 independent CTAs.
#define TILE_E (64*72)
__global__ void __launch_bounds__(128, 4) attn_kernel(){
    extern __shared__ __nv_bfloat16 dsm[];   // [K0 K1 K2 V0 V1 V2], 64x72 each

    const int bh = blockIdx.y;
    const int n0 = blockIdx.x * 64;
    const int tid  = threadIdx.x;
    const int lane = tid & 31;
    const int warp = tid >> 5;               // 0..3, owns rows [warp*16, +16)
    const int g = lane >> 2, t = lane & 3;

    const int sel   = lane >> 3;
    const int n_off = ((sel >> 1) << 3) + (lane & 7);   // 0..15
    const int c_off = (sel & 1) << 3;                   // 0 or 8

    const __nv_bfloat16* qtb = g_qT + (size_t)bh*N_*HD_;
    const __nv_bfloat16* ktb = g_kT + (size_t)bh*N_*HD_;
    const __nv_bfloat16* vb  = g_v  + (size_t)bh*HD_*N_;

    __nv_bfloat16* KS = dsm;
    __nv_bfloat16* VS = dsm + 3*TILE_E;

    // Q fragments in registers (scale already folded), M=16
    uint32_t qa[4][4];
    {
        const __nv_bfloat16* ra = qtb + (size_t)(n0 + warp*16 + g)*HD_;
        const __nv_bfloat16* rb = ra + 8*HD_;
        #pragma unroll
        for (int kk=0; kk<4; kk++){
            qa[kk][0] = lds32(ra + kk*16     + t*2);
            qa[kk][1] = lds32(rb + kk*16     + t*2);
            qa[kk][2] = lds32(ra + kk*16 + 8 + t*2);
            qa[kk][3] = lds32(rb + kk*16 + 8 + t*2);
        }
    }

    float o[8][4];
    #pragma unroll
    for (int nb=0; nb<8; nb++)
        #pragma unroll
        for (int r=0; r<4; r++) o[nb][r] = 0.f;
    float lsum0 = 0.f, lsum1 = 0.f;

    const int frow = tid >> 3;               // 0..15 (+p*16)
    const int fc8  = (tid & 7) * 8;

    // prologue: K,V tile 0 -> slot 0
    #pragma unroll
    for (int p=0; p<4; p++){
        int row = frow + p*16;
        cpasync16(KS + row*72 + fc8, ktb + (size_t)row*HD_ + fc8);
        cpasync16(VS + row*72 + fc8, vb + (size_t)row*N_ + fc8);
    }
    cp_commit();

    int s_cur = 0, s_nxt = 1;
    for (int kt = 0; kt < N_/64; kt++){
        if (kt + 1 < N_/64){
            __nv_bfloat16* kd = KS + s_nxt*TILE_E;
            __nv_bfloat16* vd = VS + s_nxt*TILE_E;
            const __nv_bfloat16* ksrc = ktb + (size_t)(kt+1)*64*HD_;
            const __nv_bfloat16* vsrc = vb + (size_t)(kt+1)*64;
            #pragma unroll
            for (int p=0; p<4; p++){
                int row = frow + p*16;
                cpasync16(kd + row*72 + fc8, ksrc + (size_t)row*HD_ + fc8);
                cpasync16(vd + row*72 + fc8, vsrc + (size_t)row*N_ + fc8);
            }
            cp_commit();
            asm volatile("cp.async.wait_group 1;\n");
        } else {
            asm volatile("cp.async.wait_group 0;\n");
        }
        __syncthreads();   // the ONLY barrier per iteration (intra-CTA only)

        const __nv_bfloat16* kb_s = KS + s_cur*TILE_E;
        const __nv_bfloat16* vb_s = VS + s_cur*TILE_E;

        // ---- S = Q K^T (M=16, N=64) ----
        float s[8][4];
        #pragma unroll
        for (int nb=0; nb<8; nb++)
            #pragma unroll
            for (int r=0; r<4; r++) s[nb][r] = 0.f;
        #pragma unroll
        for (int kk=0; kk<4; kk++){
            #pragma unroll
            for (int nbp=0; nbp<4; nbp++){
                uint32_t b0,b1,b2,b3;
                ldsm4(b0,b1,b2,b3, kb_s + (nbp*16 + n_off)*72 + kk*16 + c_off);
                mma16816(s[2*nbp  ], qa[kk][0],qa[kk][1],qa[kk][2],qa[kk][3], b0,b1);
                mma16816(s[2*nbp+1], qa[kk][0],qa[kk][1],qa[kk][2],qa[kk][3], b2,b3);
            }
        }

        // ---- exp2 + per-lane l accumulation ----
        #pragma unroll
        for (int nb=0; nb<8; nb++){
            s[nb][0] = ex2(s[nb][0]);
            s[nb][1] = ex2(s[nb][1]);
            s[nb][2] = ex2(s[nb][2]);
            s[nb][3] = ex2(s[nb][3]);
            lsum0 += s[nb][0] + s[nb][1];
            lsum1 += s[nb][2] + s[nb][3];
        }

        // ---- O += P V^T ----
        #pragma unroll
        for (int kb=0; kb<4; kb++){
            uint32_t pa0 = f2b2(s[2*kb  ][0], s[2*kb  ][1]);
            uint32_t pa1 = f2b2(s[2*kb  ][2], s[2*kb  ][3]);
            uint32_t pa2 = f2b2(s[2*kb+1][0], s[2*kb+1][1]);
            uint32_t pa3 = f2b2(s[2*kb+1][2], s[2*kb+1][3]);
            #pragma unroll
            for (int nbp=0; nbp<4; nbp++){
                uint32_t b0,b1,b2,b3;
                ldsm4(b0,b1,b2,b3, vb_s + (nbp*16 + n_off)*72 + kb*16 + c_off);
                mma16816(o[2*nbp  ], pa0,pa1,pa2,pa3, b0,b1);
                mma16816(o[2*nbp+1], pa0,pa1,pa2,pa3, b2,b3);
            }
        }

        s_cur = s_nxt;
        s_nxt = (s_nxt == 2) ? 0 : s_nxt + 1;
    }

    // ---- epilogue: cross-lane l reduction, normalize, store [b][n][c] ----
    const int batch = bh >> 2, h = bh & 3;
    __nv_bfloat16* aot = g_aoT + (size_t)batch*N_*C_ + h*64;
    {
        float l0 = lsum0, l1 = lsum1;
        l0 += __shfl_xor_sync(0xffffffffu, l0, 1);
        l0 += __shfl_xor_sync(0xffffffffu, l0, 2);
        l1 += __shfl_xor_sync(0xffffffffu, l1, 1);
        l1 += __shfl_xor_sync(0xffffffffu, l1, 2);
        float i0 = 1.f / l0, i1 = 1.f / l1;
        int r = n0 + warp*16 + g;
        #pragma unroll
        for (int nb=0; nb<8; nb++){
            int d = nb*8 + t*2;
            *reinterpret_cast<uint32_t*>(&aot[(size_t)r    *C_ + d]) =
                f2b2(o[nb][0]*i0, o[nb][1]*i0);
            *reinterpret_cast<uint32_t*>(&aot[(size_t)(r+8)*C_ + d]) =
                f2b2(o[nb][2]*i1, o[nb][3]*i1);
        }
    }
}

// ---------------- output projection + residual: depth-2 pipeline, 4 slots ------
__global__ void __launch_bounds__(256) oproj_kernel(
        const float* __restrict__ bias,
        const float* __restrict__ resid,
        float* __restrict__ outf){
    extern __shared__ __nv_bfloat16 gsm[];
    const int batch = blockIdx.z;
    const __nv_bfloat16* W  = g_wb + 3*C_*C_;
    const __nv_bfloat16* XT = g_aoT + (size_t)batch*N_*C_;

    __nv_bfloat16* AS = gsm;
    __nv_bfloat16* BS = gsm + 4*GS_SLOT;

    const int n0 = blockIdx.x * 128;
    const int m0 = blockIdx.y * 128;

    const int tid  = threadIdx.x;
    const int lane = tid & 31;
    const int warp = tid >> 5;
    const int g = lane >> 2, t = lane & 3;
    const int wm = warp >> 2, wn = warp & 3;

    const int frow = tid >> 2;
    const int fc8  = (tid & 3) * 8;

    const __nv_bfloat16* Wp = W + (size_t)m0*C_;
    const __nv_bfloat16* Xp = XT + (size_t)n0*C_;

    float c[4][4][4];
    #pragma unroll
    for (int mb=0; mb<4; mb++) for (int nb=0; nb<4; nb++)
        #pragma unroll
        for (int r=0; r<4; r++) c[mb][nb][r] = 0.f;

    GEMM_FILL(AS, BS, Wp, Xp, 0);
    cp_commit();
    GEMM_FILL(AS + GS_SLOT, BS + GS_SLOT, Wp, Xp, 32);
    cp_commit();

    for (int kt = 0; kt < 8; kt++){
        if (kt + 2 < 8){
            int sl = (kt + 2) & 3;
            GEMM_FILL(AS + sl*GS_SLOT, BS + sl*GS_SLOT, Wp, Xp, (kt+2)*32);
        }
        cp_commit();
        asm volatile("cp.async.wait_group 2;\n");
        __syncthreads();

        const __nv_bfloat16* as = AS + (kt & 3)*GS_SLOT;
        const __nv_bfloat16* bs = BS + (kt & 3)*GS_SLOT;

        #pragma unroll
        for (int kk = 0; kk < 32; kk += 16){
            uint32_t A[4][4];
            #pragma unroll
            for (int mb=0; mb<4; mb++){
                int mbase = wm*64 + mb*16;
                A[mb][0] = lds32(as + (mbase+g  )*GS_ROW + kk +   t*2);
                A[mb][1] = lds32(as + (mbase+g+8)*GS_ROW + kk +   t*2);
                A[mb][2] = lds32(as + (mbase+g  )*GS_ROW + kk+8 + t*2);
                A[mb][3] = lds32(as + (mbase+g+8)*GS_ROW + kk+8 + t*2);
            }
            #pragma unroll
            for (int nb=0; nb<4; nb++){
                uint32_t b0 = lds32(bs + (wn*32+nb*8+g)*GS_ROW + kk +   t*2);
                uint32_t b1 = lds32(bs + (wn*32+nb*8+g)*GS_ROW + kk+8 + t*2);
                #pragma unroll
                for (int mb=0; mb<4; mb++)
                    mma16816(c[mb][nb], A[mb][0],A[mb][1],A[mb][2],A[mb][3], b0,b1);
            }
        }
    }

    #pragma unroll
    for (int mb=0; mb<4; mb++){
        int m = m0 + wm*64 + mb*16 + g;
        float bv0 = bias[m], bv8 = bias[m+8];
        #pragma unroll
        for (int nb=0; nb<4; nb++){
            int n = n0 + wn*32 + nb*8 + t*2;
            size_t i0 = ((size_t)batch*C_ + m)*N_ + n;
            size_t i8 = ((size_t)batch*C_ + m + 8)*N_ + n;
            float2 r0 = *reinterpret_cast<const float2*>(&resid[i0]);
            float2 r8 = *reinterpret_cast<const float2*>(&resid[i8]);
            *reinterpret_cast<float2*>(&outf[i0]) =
                make_float2(c[mb][nb][0]+bv0+r0.x, c[mb][nb][1]+bv0+r0.y);
            *reinterpret_cast<float2*>(&outf[i8]) =
                make_float2(c[mb][nb][2]+bv8+r8.x, c[mb][nb][3]+bv8+r8.y);
        }
    }
}

// ---------------- launch ----------------
extern "C" void kernel_launch(void* const* d_in, const int* in_sizes, int n_in,
                              void* d_out, int out_size){
    const float* x    = (const float*)d_in[0];
    const float* cond = (const float*)d_in[1];
    const float* gqw  = (const float*)d_in[2];
    const float* gqb  = (const float*)d_in[3];
    const float* gkw  = (const float*)d_in[4];
    const float* gkb  = (const float*)d_in[5];
    const float* wq   = (const float*)d_in[6];
    const float* bq   = (const float*)d_in[7];
    const float* wk   = (const float*)d_in[8];
    const float* bk   = (const float*)d_in[9];
    const float* wv   = (const float*)d_in[10];
    const float* bv   = (const float*)d_in[11];
    const float* wo   = (const float*)d_in[12];
    const float* bo   = (const float*)d_in[13];
    float* out = (float*)d_out;

    const int attn_smem = 6 * TILE_E * (int)sizeof(__nv_bfloat16);   // 55296 B
    const int gemm_smem = GS_TOT * (int)sizeof(__nv_bfloat16);        // 81920 B
    cudaFuncSetAttribute(attn_kernel, cudaFuncAttributeMaxDynamicSharedMemorySize, attn_smem);
    cudaFuncSetAttribute(qkv_kernel,  cudaFuncAttributeMaxDynamicSharedMemorySize, gemm_smem);
    cudaFuncSetAttribute(oproj_kernel,cudaFuncAttributeMaxDynamicSharedMemorySize, gemm_smem);

    gn_kernel<<<dim3(128, 3), 256>>>(x, cond, gqw, gqb, gkw, gkb, wq, wk, wv, wo);
    qkv_kernel<<<dim3(32, 2, 12), 256, gemm_smem>>>(bq, bk, bv);
    attn_kernel<<<dim3(64, 16), 128, attn_smem>>>();
    oproj_kernel<<<dim3(32, 2, 4), 256, gemm_smem>>>(bo, x, out);
}